// round 5
// baseline (speedup 1.0000x reference)
#include <cuda_runtime.h>
#include <cstddef>

#define BB 4
#define HH 256
#define WW 256
#define HWPLANE (HH * WW)
#define NF 64
#define KK 15
#define KK2 (KK * KK)   // 225

__device__ float g_feat0[BB * NF * HWPLANE];
__device__ float g_feat1[BB * NF * HWPLANE];
__device__ float g_core [BB * KK2 * HWPLANE];

typedef unsigned long long u64;

__device__ __forceinline__ u64 pack2(float lo, float hi) {
    u64 r;
    asm("mov.b64 %0, {%1, %2};" : "=l"(r) : "f"(lo), "f"(hi));
    return r;
}
__device__ __forceinline__ void unpack2(u64 v, float& lo, float& hi) {
    asm("mov.b64 {%0, %1}, %2;" : "=f"(lo), "=f"(hi) : "l"(v));
}
__device__ __forceinline__ void fma2(u64& acc, u64 a, u64 b) {
    asm("fma.rn.f32x2 %0, %1, %2, %0;" : "+l"(acc) : "l"(a), "l"(b));
}

// ============================================================
// conv3x3 SAME, NCHW, fp32.
// Block: 256 threads, tile 32 wide x 64 tall, 4 out-channels.
// Thread: 2px (f32x2) x 8 rows x 2 oc = 32 outputs.
// Weights held in REGISTERS per ic (18 LDS.64 broadcast feeding
// 144 FFMA2). Rolling 3-row input window. Halo stored with a
// -1 column shift so all tap pairs are aligned LDS.64.
// ============================================================
template<int IC, bool RELU, bool RESID>
__global__ __launch_bounds__(256, 2)
void conv3x3_k(const float* __restrict__ in,
               const float* __restrict__ wgt,
               const float* __restrict__ bias,
               const float* __restrict__ resid,
               float* __restrict__ out,
               int OC, int ocGroups)
{
    __shared__ float  s_in[2][66 * 36];
    __shared__ float2 s_w[IC * 36];        // [ic][ocl(4)][tap(9)] duplicated {w,w}

    const int tid  = threadIdx.x;
    const int tX   = tid & 15;             // x pair
    const int tY   = (tid >> 4) & 7;       // 8-row band (64 rows)
    const int half = tid >> 7;             // oc pair select

    const int tile_x = blockIdx.x * 32;
    const int tile_y = blockIdx.y * 64;
    const int zb = blockIdx.z;
    const int b   = zb / ocGroups;
    const int g   = zb - b * ocGroups;
    const int oc0 = g * 4;
    const int ocA = oc0 + half * 2;

    // ---- weights to smem (duplicated pairs) ----
    for (int i = tid; i < IC * 36; i += 256) {
        int ic  = i / 36;
        int r   = i - ic * 36;
        int ocl = r / 9;
        int tap = r - ocl * 9;
        int oc  = oc0 + ocl;
        float v = (oc < OC) ? wgt[((size_t)oc * IC + ic) * 9 + tap] : 0.0f;
        s_w[i] = make_float2(v, v);
    }

    float bz[2];
#pragma unroll
    for (int o = 0; o < 2; o++)
        bz[o] = (ocA + o < OC) ? bias[ocA + o] : 0.0f;

    const float* inb = in + (size_t)b * IC * HWPLANE;

    // ---- hoisted halo addressing ----
    // halo: 66 rows (gy = tile_y-1+row), cols gx = tile_x-2 .. tile_x+33
    // loaded as 18 float2 pairs/row. smem col c' = gx - (tile_x-1), c' in 0..34.
    // pair k: v.x -> c'=2k-1 (skip if k==0), v.y -> c'=2k.
    int sy[5], gofs[5];
    unsigned skipx = 0;
#pragma unroll
    for (int j = 0; j < 5; j++) {
        int i = tid + j * 256;
        int row = i / 18, pc = i - row * 18;
        bool slot = (i < 66 * 18);
        int gy = tile_y - 1 + row;
        int gx0 = tile_x - 2 + 2 * pc;
        bool v = slot && gy >= 0 && gy < HH && gx0 >= 0 && gx0 < WW;
        gofs[j] = v ? (gy * WW + gx0) : -1;
        sy[j]   = slot ? (row * 36 + 2 * pc) * 4 : -1;
        if (pc == 0) skipx |= (1u << j);
    }

    // ---- stage ic = 0 ----
    {
        const float* plane = inb;
        float2 pv[5];
#pragma unroll
        for (int j = 0; j < 5; j++)
            pv[j] = (gofs[j] >= 0) ? *reinterpret_cast<const float2*>(plane + gofs[j])
                                   : make_float2(0.0f, 0.0f);
        char* dst = (char*)s_in[0];
#pragma unroll
        for (int j = 0; j < 5; j++) {
            if (sy[j] >= 0) {
                *reinterpret_cast<float*>(dst + sy[j]) = pv[j].y;
                if (!((skipx >> j) & 1))
                    *reinterpret_cast<float*>(dst + sy[j] - 4) = pv[j].x;
            }
        }
    }
    __syncthreads();

    u64 acc[2][8];
#pragma unroll
    for (int o = 0; o < 2; o++) {
        u64 bb2 = pack2(bz[o], bz[o]);
#pragma unroll
        for (int r = 0; r < 8; r++) acc[o][r] = bb2;
    }

    int buf = 0;
#pragma unroll 1
    for (int ic = 0; ic < IC; ++ic) {
        // prefetch next channel (global loads issued before compute)
        float2 pv[5];
        const bool more = (ic + 1 < IC);
        if (more) {
            const float* plane = inb + (size_t)(ic + 1) * HWPLANE;
#pragma unroll
            for (int j = 0; j < 5; j++)
                pv[j] = (gofs[j] >= 0) ? *reinterpret_cast<const float2*>(plane + gofs[j])
                                       : make_float2(0.0f, 0.0f);
        }

        // weights for this ic into registers
        u64 w[2][9];
        {
            const float2* Wc = &s_w[ic * 36 + half * 18];
#pragma unroll
            for (int ocl = 0; ocl < 2; ocl++)
#pragma unroll
                for (int tap = 0; tap < 9; tap++)
                    w[ocl][tap] = *reinterpret_cast<const u64*>(&Wc[ocl * 9 + tap]);
        }

        const float* S = s_in[buf] + (8 * tY) * 36 + 2 * tX;

        // rolling 3-row window
        u64 p[3][3];
#pragma unroll
        for (int h = 0; h < 3; h++) {
            const float* row = S + h * 36;
            u64 A = *reinterpret_cast<const u64*>(row);
            u64 B = *reinterpret_cast<const u64*>(row + 2);
            float a0, a1, b0, b1;
            unpack2(A, a0, a1); unpack2(B, b0, b1);
            p[h][0] = A; p[h][1] = pack2(a1, b0); p[h][2] = B;
        }

#pragma unroll
        for (int r = 0; r < 8; r++) {
#pragma unroll
            for (int ki = 0; ki < 3; ki++) {
                const int slot = (r + ki) % 3;
#pragma unroll
                for (int kj = 0; kj < 3; kj++) {
                    fma2(acc[0][r], p[slot][kj], w[0][ki * 3 + kj]);
                    fma2(acc[1][r], p[slot][kj], w[1][ki * 3 + kj]);
                }
            }
            if (r < 7) {
                const int slot = r % 3;
                const float* row = S + (r + 3) * 36;
                u64 A = *reinterpret_cast<const u64*>(row);
                u64 B = *reinterpret_cast<const u64*>(row + 2);
                float a0, a1, b0, b1;
                unpack2(A, a0, a1); unpack2(B, b0, b1);
                p[slot][0] = A; p[slot][1] = pack2(a1, b0); p[slot][2] = B;
            }
        }

        // stage next channel into other buffer
        if (more) {
            char* dst = (char*)s_in[buf ^ 1];
#pragma unroll
            for (int j = 0; j < 5; j++) {
                if (sy[j] >= 0) {
                    *reinterpret_cast<float*>(dst + sy[j]) = pv[j].y;
                    if (!((skipx >> j) & 1))
                        *reinterpret_cast<float*>(dst + sy[j] - 4) = pv[j].x;
                }
            }
        }
        __syncthreads();
        buf ^= 1;
    }

    // ---- store ----
    const int x0 = tile_x + 2 * tX;
#pragma unroll
    for (int ocl = 0; ocl < 2; ocl++) {
        int oc = ocA + ocl;
        if (oc >= OC) break;
        size_t base = ((size_t)b * OC + oc) * HWPLANE;
#pragma unroll
        for (int dy = 0; dy < 8; dy++) {
            int y = tile_y + 8 * tY + dy;
            float f0, f1;
            unpack2(acc[ocl][dy], f0, f1);
            size_t idx = base + (size_t)y * WW + x0;
            if (RELU) { f0 = fmaxf(f0, 0.0f); f1 = fmaxf(f1, 0.0f); }
            if (RESID) {
                float2 rv = *reinterpret_cast<const float2*>(resid + idx);
                f0 += rv.x; f1 += rv.y;
            }
            *reinterpret_cast<float2*>(out + idx) = make_float2(f0, f1);
        }
    }
}

// ============================================================
// kernel_conv: softmax(|core|) over 225 taps + dynamic filter
// ============================================================
__global__ __launch_bounds__(256)
void kpn_apply_k(const float* __restrict__ core,
                 const float* __restrict__ data,
                 float* __restrict__ pred)
{
    __shared__ float s_data[3][30][32];

    const int tid = threadIdx.x;
    const int lx = tid & 15;
    const int ly = tid >> 4;
    const int tile_x = blockIdx.x * 16;
    const int tile_y = blockIdx.y * 16;
    const int b = blockIdx.z;

    for (int i = tid; i < 3 * 30 * 30; i += 256) {
        int c = i / 900;
        int r = (i - c * 900) / 30;
        int col = i - c * 900 - r * 30;
        int gy = tile_y - 7 + r;
        int gx = tile_x - 7 + col;
        float v = 0.0f;
        if (gy >= 0 && gy < HH && gx >= 0 && gx < WW)
            v = data[((size_t)b * 3 + c) * HWPLANE + gy * WW + gx];
        s_data[c][r][col] = v;
    }
    __syncthreads();

    const int y = tile_y + ly;
    const int x = tile_x + lx;
    const float* cb = core + (size_t)b * KK2 * HWPLANE + (size_t)y * WW + x;

    float S = 0.0f, P0 = 0.0f, P1 = 0.0f, P2 = 0.0f;

    for (int ki = 0; ki < KK; ki++) {
#pragma unroll
        for (int kj = 0; kj < KK; kj++) {
            float c = cb[(size_t)(ki * KK + kj) * HWPLANE];
            float w = __expf(fabsf(c));
            S += w;
            P0 += w * s_data[0][ly + ki][lx + kj];
            P1 += w * s_data[1][ly + ki][lx + kj];
            P2 += w * s_data[2][ly + ki][lx + kj];
        }
    }

    float inv = 1.0f / S;
    size_t o = (size_t)b * 3 * HWPLANE + (size_t)y * WW + x;
    pred[o]                = P0 * inv;
    pred[o + HWPLANE]      = P1 * inv;
    pred[o + 2 * HWPLANE]  = P2 * inv;
}

static float* sym_addr(const void* s)
{
    void* p = nullptr;
    cudaGetSymbolAddress(&p, s);
    return (float*)p;
}

extern "C" void kernel_launch(void* const* d_in, const int* in_sizes, int n_in,
                              void* d_out, int out_size)
{
    const float* dwe     = (const float*)d_in[0];
    const float* data    = (const float*)d_in[1];
    const float* w_first = (const float*)d_in[2];
    const float* b_first = (const float*)d_in[3];
    const float* w1a = (const float*)d_in[4];
    const float* b1a = (const float*)d_in[5];
    const float* w1b = (const float*)d_in[6];
    const float* b1b = (const float*)d_in[7];
    const float* w2a = (const float*)d_in[8];
    const float* b2a = (const float*)d_in[9];
    const float* w2b = (const float*)d_in[10];
    const float* b2b = (const float*)d_in[11];
    const float* w3a = (const float*)d_in[12];
    const float* b3a = (const float*)d_in[13];
    const float* w3b = (const float*)d_in[14];
    const float* b3b = (const float*)d_in[15];
    const float* w_out = (const float*)d_in[16];
    const float* b_out = (const float*)d_in[17];

    float* f0   = sym_addr(g_feat0);
    float* f1   = sym_addr(g_feat1);
    float* core = sym_addr(g_core);

    dim3 blk(256);
    dim3 grid64(WW / 32, HH / 64, BB * (NF / 4));       // 8,4,64
    const int ocGroupsOut = (KK2 + 3) / 4;              // 57
    dim3 gridOut(WW / 32, HH / 64, BB * ocGroupsOut);   // 8,4,228

    conv3x3_k<6, false, false><<<grid64, blk>>>(dwe, w_first, b_first, nullptr, f0, NF, NF / 4);

    conv3x3_k<64, true,  false><<<grid64, blk>>>(f0, w1a, b1a, nullptr, f1, NF, NF / 4);
    conv3x3_k<64, false, true ><<<grid64, blk>>>(f1, w1b, b1b, f0,      f0, NF, NF / 4);
    conv3x3_k<64, true,  false><<<grid64, blk>>>(f0, w2a, b2a, nullptr, f1, NF, NF / 4);
    conv3x3_k<64, false, true ><<<grid64, blk>>>(f1, w2b, b2b, f0,      f0, NF, NF / 4);
    conv3x3_k<64, true,  false><<<grid64, blk>>>(f0, w3a, b3a, nullptr, f1, NF, NF / 4);
    conv3x3_k<64, false, true ><<<grid64, blk>>>(f1, w3b, b3b, f0,      f0, NF, NF / 4);

    conv3x3_k<64, false, false><<<gridOut, blk>>>(f0, w_out, b_out, nullptr, core, KK2, ocGroupsOut);

    cudaMemcpyAsync(d_out, data, (size_t)BB * 3 * HWPLANE * sizeof(float),
                    cudaMemcpyDeviceToDevice, 0);

    dim3 gridK(WW / 16, HH / 16, BB);
    kpn_apply_k<<<gridK, blk>>>(core, data, (float*)d_out + (size_t)BB * 3 * HWPLANE);
}

// round 6
// speedup vs baseline: 1.0003x; 1.0003x over previous
#include <cuda_runtime.h>
#include <cstddef>

#define BB 4
#define HH 256
#define WW 256
#define HWPLANE (HH * WW)
#define NF 64
#define KK 15
#define KK2 (KK * KK)   // 225

__device__ float g_feat0[BB * NF * HWPLANE];
__device__ float g_feat1[BB * NF * HWPLANE];
__device__ float g_core [BB * KK2 * HWPLANE];

typedef unsigned long long u64;

__device__ __forceinline__ u64 pack2(float lo, float hi) {
    u64 r;
    asm("mov.b64 %0, {%1, %2};" : "=l"(r) : "f"(lo), "f"(hi));
    return r;
}
__device__ __forceinline__ void unpack2(u64 v, float& lo, float& hi) {
    asm("mov.b64 {%0, %1}, %2;" : "=f"(lo), "=f"(hi) : "l"(v));
}
__device__ __forceinline__ void fma2(u64& acc, u64 a, u64 b) {
    asm("fma.rn.f32x2 %0, %1, %2, %0;" : "+l"(acc) : "l"(a), "l"(b));
}

// ============================================================
// conv3x3 SAME, NCHW, fp32.
// Block: 256 threads, tile 32 wide x 64 tall, 4 out-channels.
// Thread: 2px (f32x2) x 8 rows x 2 oc = 32 outputs.
// Weights held in REGISTERS per ic (18 LDS.64 broadcast feeding
// 144 FFMA2). Rolling 3-row input window. Halo stored with a
// -1 column shift so all tap pairs are aligned LDS.64.
// ============================================================
template<int IC, bool RELU, bool RESID>
__global__ __launch_bounds__(256, 2)
void conv3x3_k(const float* __restrict__ in,
               const float* __restrict__ wgt,
               const float* __restrict__ bias,
               const float* __restrict__ resid,
               float* __restrict__ out,
               int OC, int ocGroups)
{
    __shared__ float  s_in[2][66 * 36];
    __shared__ float2 s_w[IC * 36];        // [ic][ocl(4)][tap(9)] duplicated {w,w}

    const int tid  = threadIdx.x;
    const int tX   = tid & 15;             // x pair
    const int tY   = (tid >> 4) & 7;       // 8-row band (64 rows)
    const int half = tid >> 7;             // oc pair select

    const int tile_x = blockIdx.x * 32;
    const int tile_y = blockIdx.y * 64;
    const int zb = blockIdx.z;
    const int b   = zb / ocGroups;
    const int g   = zb - b * ocGroups;
    const int oc0 = g * 4;
    const int ocA = oc0 + half * 2;

    // ---- weights to smem (duplicated pairs) ----
    for (int i = tid; i < IC * 36; i += 256) {
        int ic  = i / 36;
        int r   = i - ic * 36;
        int ocl = r / 9;
        int tap = r - ocl * 9;
        int oc  = oc0 + ocl;
        float v = (oc < OC) ? wgt[((size_t)oc * IC + ic) * 9 + tap] : 0.0f;
        s_w[i] = make_float2(v, v);
    }

    float bz[2];
#pragma unroll
    for (int o = 0; o < 2; o++)
        bz[o] = (ocA + o < OC) ? bias[ocA + o] : 0.0f;

    const float* inb = in + (size_t)b * IC * HWPLANE;

    // ---- hoisted halo addressing ----
    // halo: 66 rows (gy = tile_y-1+row), cols gx = tile_x-2 .. tile_x+33
    // loaded as 18 float2 pairs/row. smem col c' = gx - (tile_x-1), c' in 0..34.
    // pair k: v.x -> c'=2k-1 (skip if k==0), v.y -> c'=2k.
    int sy[5], gofs[5];
    unsigned skipx = 0;
#pragma unroll
    for (int j = 0; j < 5; j++) {
        int i = tid + j * 256;
        int row = i / 18, pc = i - row * 18;
        bool slot = (i < 66 * 18);
        int gy = tile_y - 1 + row;
        int gx0 = tile_x - 2 + 2 * pc;
        bool v = slot && gy >= 0 && gy < HH && gx0 >= 0 && gx0 < WW;
        gofs[j] = v ? (gy * WW + gx0) : -1;
        sy[j]   = slot ? (row * 36 + 2 * pc) * 4 : -1;
        if (pc == 0) skipx |= (1u << j);
    }

    // ---- stage ic = 0 ----
    {
        const float* plane = inb;
        float2 pv[5];
#pragma unroll
        for (int j = 0; j < 5; j++)
            pv[j] = (gofs[j] >= 0) ? *reinterpret_cast<const float2*>(plane + gofs[j])
                                   : make_float2(0.0f, 0.0f);
        char* dst = (char*)s_in[0];
#pragma unroll
        for (int j = 0; j < 5; j++) {
            if (sy[j] >= 0) {
                *reinterpret_cast<float*>(dst + sy[j]) = pv[j].y;
                if (!((skipx >> j) & 1))
                    *reinterpret_cast<float*>(dst + sy[j] - 4) = pv[j].x;
            }
        }
    }
    __syncthreads();

    u64 acc[2][8];
#pragma unroll
    for (int o = 0; o < 2; o++) {
        u64 bb2 = pack2(bz[o], bz[o]);
#pragma unroll
        for (int r = 0; r < 8; r++) acc[o][r] = bb2;
    }

    int buf = 0;
#pragma unroll 1
    for (int ic = 0; ic < IC; ++ic) {
        // prefetch next channel (global loads issued before compute)
        float2 pv[5];
        const bool more = (ic + 1 < IC);
        if (more) {
            const float* plane = inb + (size_t)(ic + 1) * HWPLANE;
#pragma unroll
            for (int j = 0; j < 5; j++)
                pv[j] = (gofs[j] >= 0) ? *reinterpret_cast<const float2*>(plane + gofs[j])
                                       : make_float2(0.0f, 0.0f);
        }

        // weights for this ic into registers
        u64 w[2][9];
        {
            const float2* Wc = &s_w[ic * 36 + half * 18];
#pragma unroll
            for (int ocl = 0; ocl < 2; ocl++)
#pragma unroll
                for (int tap = 0; tap < 9; tap++)
                    w[ocl][tap] = *reinterpret_cast<const u64*>(&Wc[ocl * 9 + tap]);
        }

        const float* S = s_in[buf] + (8 * tY) * 36 + 2 * tX;

        // rolling 3-row window
        u64 p[3][3];
#pragma unroll
        for (int h = 0; h < 3; h++) {
            const float* row = S + h * 36;
            u64 A = *reinterpret_cast<const u64*>(row);
            u64 B = *reinterpret_cast<const u64*>(row + 2);
            float a0, a1, b0, b1;
            unpack2(A, a0, a1); unpack2(B, b0, b1);
            p[h][0] = A; p[h][1] = pack2(a1, b0); p[h][2] = B;
        }

#pragma unroll
        for (int r = 0; r < 8; r++) {
#pragma unroll
            for (int ki = 0; ki < 3; ki++) {
                const int slot = (r + ki) % 3;
#pragma unroll
                for (int kj = 0; kj < 3; kj++) {
                    fma2(acc[0][r], p[slot][kj], w[0][ki * 3 + kj]);
                    fma2(acc[1][r], p[slot][kj], w[1][ki * 3 + kj]);
                }
            }
            if (r < 7) {
                const int slot = r % 3;
                const float* row = S + (r + 3) * 36;
                u64 A = *reinterpret_cast<const u64*>(row);
                u64 B = *reinterpret_cast<const u64*>(row + 2);
                float a0, a1, b0, b1;
                unpack2(A, a0, a1); unpack2(B, b0, b1);
                p[slot][0] = A; p[slot][1] = pack2(a1, b0); p[slot][2] = B;
            }
        }

        // stage next channel into other buffer
        if (more) {
            char* dst = (char*)s_in[buf ^ 1];
#pragma unroll
            for (int j = 0; j < 5; j++) {
                if (sy[j] >= 0) {
                    *reinterpret_cast<float*>(dst + sy[j]) = pv[j].y;
                    if (!((skipx >> j) & 1))
                        *reinterpret_cast<float*>(dst + sy[j] - 4) = pv[j].x;
                }
            }
        }
        __syncthreads();
        buf ^= 1;
    }

    // ---- store ----
    const int x0 = tile_x + 2 * tX;
#pragma unroll
    for (int ocl = 0; ocl < 2; ocl++) {
        int oc = ocA + ocl;
        if (oc >= OC) break;
        size_t base = ((size_t)b * OC + oc) * HWPLANE;
#pragma unroll
        for (int dy = 0; dy < 8; dy++) {
            int y = tile_y + 8 * tY + dy;
            float f0, f1;
            unpack2(acc[ocl][dy], f0, f1);
            size_t idx = base + (size_t)y * WW + x0;
            if (RELU) { f0 = fmaxf(f0, 0.0f); f1 = fmaxf(f1, 0.0f); }
            if (RESID) {
                float2 rv = *reinterpret_cast<const float2*>(resid + idx);
                f0 += rv.x; f1 += rv.y;
            }
            *reinterpret_cast<float2*>(out + idx) = make_float2(f0, f1);
        }
    }
}

// ============================================================
// kernel_conv: softmax(|core|) over 225 taps + dynamic filter
// ============================================================
__global__ __launch_bounds__(256)
void kpn_apply_k(const float* __restrict__ core,
                 const float* __restrict__ data,
                 float* __restrict__ pred)
{
    __shared__ float s_data[3][30][32];

    const int tid = threadIdx.x;
    const int lx = tid & 15;
    const int ly = tid >> 4;
    const int tile_x = blockIdx.x * 16;
    const int tile_y = blockIdx.y * 16;
    const int b = blockIdx.z;

    for (int i = tid; i < 3 * 30 * 30; i += 256) {
        int c = i / 900;
        int r = (i - c * 900) / 30;
        int col = i - c * 900 - r * 30;
        int gy = tile_y - 7 + r;
        int gx = tile_x - 7 + col;
        float v = 0.0f;
        if (gy >= 0 && gy < HH && gx >= 0 && gx < WW)
            v = data[((size_t)b * 3 + c) * HWPLANE + gy * WW + gx];
        s_data[c][r][col] = v;
    }
    __syncthreads();

    const int y = tile_y + ly;
    const int x = tile_x + lx;
    const float* cb = core + (size_t)b * KK2 * HWPLANE + (size_t)y * WW + x;

    float S = 0.0f, P0 = 0.0f, P1 = 0.0f, P2 = 0.0f;

    for (int ki = 0; ki < KK; ki++) {
#pragma unroll
        for (int kj = 0; kj < KK; kj++) {
            float c = cb[(size_t)(ki * KK + kj) * HWPLANE];
            float w = __expf(fabsf(c));
            S += w;
            P0 += w * s_data[0][ly + ki][lx + kj];
            P1 += w * s_data[1][ly + ki][lx + kj];
            P2 += w * s_data[2][ly + ki][lx + kj];
        }
    }

    float inv = 1.0f / S;
    size_t o = (size_t)b * 3 * HWPLANE + (size_t)y * WW + x;
    pred[o]                = P0 * inv;
    pred[o + HWPLANE]      = P1 * inv;
    pred[o + 2 * HWPLANE]  = P2 * inv;
}

static float* sym_addr(const void* s)
{
    void* p = nullptr;
    cudaGetSymbolAddress(&p, s);
    return (float*)p;
}

extern "C" void kernel_launch(void* const* d_in, const int* in_sizes, int n_in,
                              void* d_out, int out_size)
{
    const float* dwe     = (const float*)d_in[0];
    const float* data    = (const float*)d_in[1];
    const float* w_first = (const float*)d_in[2];
    const float* b_first = (const float*)d_in[3];
    const float* w1a = (const float*)d_in[4];
    const float* b1a = (const float*)d_in[5];
    const float* w1b = (const float*)d_in[6];
    const float* b1b = (const float*)d_in[7];
    const float* w2a = (const float*)d_in[8];
    const float* b2a = (const float*)d_in[9];
    const float* w2b = (const float*)d_in[10];
    const float* b2b = (const float*)d_in[11];
    const float* w3a = (const float*)d_in[12];
    const float* b3a = (const float*)d_in[13];
    const float* w3b = (const float*)d_in[14];
    const float* b3b = (const float*)d_in[15];
    const float* w_out = (const float*)d_in[16];
    const float* b_out = (const float*)d_in[17];

    float* f0   = sym_addr(g_feat0);
    float* f1   = sym_addr(g_feat1);
    float* core = sym_addr(g_core);

    dim3 blk(256);
    dim3 grid64(WW / 32, HH / 64, BB * (NF / 4));       // 8,4,64
    const int ocGroupsOut = (KK2 + 3) / 4;              // 57
    dim3 gridOut(WW / 32, HH / 64, BB * ocGroupsOut);   // 8,4,228

    conv3x3_k<6, false, false><<<grid64, blk>>>(dwe, w_first, b_first, nullptr, f0, NF, NF / 4);

    conv3x3_k<64, true,  false><<<grid64, blk>>>(f0, w1a, b1a, nullptr, f1, NF, NF / 4);
    conv3x3_k<64, false, true ><<<grid64, blk>>>(f1, w1b, b1b, f0,      f0, NF, NF / 4);
    conv3x3_k<64, true,  false><<<grid64, blk>>>(f0, w2a, b2a, nullptr, f1, NF, NF / 4);
    conv3x3_k<64, false, true ><<<grid64, blk>>>(f1, w2b, b2b, f0,      f0, NF, NF / 4);
    conv3x3_k<64, true,  false><<<grid64, blk>>>(f0, w3a, b3a, nullptr, f1, NF, NF / 4);
    conv3x3_k<64, false, true ><<<grid64, blk>>>(f1, w3b, b3b, f0,      f0, NF, NF / 4);

    conv3x3_k<64, false, false><<<gridOut, blk>>>(f0, w_out, b_out, nullptr, core, KK2, ocGroupsOut);

    cudaMemcpyAsync(d_out, data, (size_t)BB * 3 * HWPLANE * sizeof(float),
                    cudaMemcpyDeviceToDevice, 0);

    dim3 gridK(WW / 16, HH / 16, BB);
    kpn_apply_k<<<gridK, blk>>>(core, data, (float*)d_out + (size_t)BB * 3 * HWPLANE);
}

// round 7
// speedup vs baseline: 1.0427x; 1.0424x over previous
#include <cuda_runtime.h>
#include <cstddef>

#define BB 4
#define HH 256
#define WW 256
#define HWPLANE (HH * WW)
#define NF 64
#define KK 15
#define KK2 (KK * KK)   // 225

__device__ float g_feat0[BB * NF * HWPLANE];
__device__ float g_feat1[BB * NF * HWPLANE];
__device__ float g_core [BB * KK2 * HWPLANE];

typedef unsigned long long u64;

__device__ __forceinline__ u64 pack2(float lo, float hi) {
    u64 r;
    asm("mov.b64 %0, {%1, %2};" : "=l"(r) : "f"(lo), "f"(hi));
    return r;
}
__device__ __forceinline__ void unpack2(u64 v, float& lo, float& hi) {
    asm("mov.b64 {%0, %1}, %2;" : "=f"(lo), "=f"(hi) : "l"(v));
}
__device__ __forceinline__ void fma2(u64& acc, u64 a, u64 b) {
    asm("fma.rn.f32x2 %0, %1, %2, %0;" : "+l"(acc) : "l"(a), "l"(b));
}

// ============================================================
// conv3x3 SAME, NCHW, fp32.
// Block: 256 threads, tile 32 wide x 64 tall, 4 out-channels.
// Thread: 2px (f32x2) x 8 rows x 2 oc = 32 outputs.
// 2 input channels per barrier stage (4 halo buffers); both
// next planes prefetched at stage start; weights via LDS.128.
// ============================================================
template<int IC, bool RELU, bool RESID>
__global__ __launch_bounds__(256, 2)
void conv3x3_k(const float* __restrict__ in,
               const float* __restrict__ wgt,
               const float* __restrict__ bias,
               const float* __restrict__ resid,
               float* __restrict__ out,
               int OC, int ocGroups)
{
    __shared__ float s_in[4][66 * 36];                 // 4 x 9.3KB
    __shared__ alignas(16) u64 s_w[IC * 40];           // [ic][ocl(4)][tap(10 padded)]

    const int tid  = threadIdx.x;
    const int tX   = tid & 15;
    const int tY   = (tid >> 4) & 7;
    const int half = tid >> 7;

    const int tile_x = blockIdx.x * 32;
    const int tile_y = blockIdx.y * 64;
    const int zb = blockIdx.z;
    const int b   = zb / ocGroups;
    const int g   = zb - b * ocGroups;
    const int oc0 = g * 4;
    const int ocA = oc0 + half * 2;

    // ---- weights into smem: duplicated pairs, lane padded to 10 ----
    for (int i = tid; i < IC * 40; i += 256) {
        int ic  = i / 40;
        int r   = i - ic * 40;
        int ocl = r / 10;
        int tap = r - ocl * 10;
        int oc  = oc0 + ocl;
        float v = (oc < OC && tap < 9) ? wgt[((size_t)oc * IC + ic) * 9 + tap] : 0.0f;
        s_w[i] = pack2(v, v);
    }

    float bz[2];
#pragma unroll
    for (int o = 0; o < 2; o++)
        bz[o] = (ocA + o < OC) ? bias[ocA + o] : 0.0f;

    const float* inb = in + (size_t)b * IC * HWPLANE;

    // ---- hoisted halo addressing (66 rows x 18 float2 pairs) ----
    // smem col c' = gx - (tile_x-1); pair k: v.x -> c'=2k-1 (skip k==0), v.y -> c'=2k
    int sy[5], gofs[5];
    unsigned skipx = 0;
#pragma unroll
    for (int j = 0; j < 5; j++) {
        int i = tid + j * 256;
        int row = i / 18, pc = i - row * 18;
        bool slot = (i < 66 * 18);
        int gy = tile_y - 1 + row;
        int gx0 = tile_x - 2 + 2 * pc;
        bool v = slot && gy >= 0 && gy < HH && gx0 >= 0 && gx0 < WW;
        gofs[j] = v ? (gy * WW + gx0) : -1;
        sy[j]   = slot ? (row * 36 + 2 * pc) * 4 : -1;
        if (pc == 0) skipx |= (1u << j);
    }

    // ---- stage channels 0,1 into buffers 0,1 ----
#pragma unroll
    for (int c = 0; c < 2 && c < IC; c++) {
        const float* plane = inb + (size_t)c * HWPLANE;
        float2 pv[5];
#pragma unroll
        for (int j = 0; j < 5; j++)
            pv[j] = (gofs[j] >= 0) ? *reinterpret_cast<const float2*>(plane + gofs[j])
                                   : make_float2(0.0f, 0.0f);
        char* dst = (char*)s_in[c];
#pragma unroll
        for (int j = 0; j < 5; j++) {
            if (sy[j] >= 0) {
                *reinterpret_cast<float*>(dst + sy[j]) = pv[j].y;
                if (!((skipx >> j) & 1))
                    *reinterpret_cast<float*>(dst + sy[j] - 4) = pv[j].x;
            }
        }
    }
    __syncthreads();

    u64 acc[2][8];
#pragma unroll
    for (int o = 0; o < 2; o++) {
        u64 bb2 = pack2(bz[o], bz[o]);
#pragma unroll
        for (int r = 0; r < 8; r++) acc[o][r] = bb2;
    }

    const int rowOff = (8 * tY) * 36 + 2 * tX;

    // compute one input channel from buffer S with weights for ic
    auto compute_ic = [&](const float* S, int ic) {
        // weights: 4 LDS.128 + 1 LDS.64 per oc
        u64 w[2][9];
        {
            const u64* Wc = &s_w[ic * 40 + half * 20];
#pragma unroll
            for (int ocl = 0; ocl < 2; ocl++) {
#pragma unroll
                for (int q = 0; q < 4; q++) {
                    ulonglong2 t = *reinterpret_cast<const ulonglong2*>(Wc + ocl * 10 + 2 * q);
                    w[ocl][2 * q] = t.x; w[ocl][2 * q + 1] = t.y;
                }
                w[ocl][8] = Wc[ocl * 10 + 8];
            }
        }
        u64 p[3][3];
#pragma unroll
        for (int h = 0; h < 3; h++) {
            const float* row = S + h * 36;
            u64 A = *reinterpret_cast<const u64*>(row);
            u64 B = *reinterpret_cast<const u64*>(row + 2);
            float a0, a1, b0, b1;
            unpack2(A, a0, a1); unpack2(B, b0, b1);
            p[h][0] = A; p[h][1] = pack2(a1, b0); p[h][2] = B;
        }
#pragma unroll
        for (int r = 0; r < 8; r++) {
#pragma unroll
            for (int ki = 0; ki < 3; ki++) {
                const int slot = (r + ki) % 3;
#pragma unroll
                for (int kj = 0; kj < 3; kj++) {
                    fma2(acc[0][r], p[slot][kj], w[0][ki * 3 + kj]);
                    fma2(acc[1][r], p[slot][kj], w[1][ki * 3 + kj]);
                }
            }
            if (r < 7) {
                const int slot = r % 3;
                const float* row = S + (r + 3) * 36;
                u64 A = *reinterpret_cast<const u64*>(row);
                u64 B = *reinterpret_cast<const u64*>(row + 2);
                float a0, a1, b0, b1;
                unpack2(A, a0, a1); unpack2(B, b0, b1);
                p[slot][0] = A; p[slot][1] = pack2(a1, b0); p[slot][2] = B;
            }
        }
    };

    const int nStages = (IC + 1) / 2;
#pragma unroll 1
    for (int s = 0; s < nStages; ++s) {
        const int icBase  = 2 * s;
        const int curBase = (s & 1) * 2;
        const int nxtBase = ((s + 1) & 1) * 2;

        // prefetch both planes of the next stage (independent LDGs, MLP=10)
        float2 pv0[5], pv1[5];
        const bool more0 = (icBase + 2 < IC);
        const bool more1 = (icBase + 3 < IC);
        if (more0) {
            const float* plane = inb + (size_t)(icBase + 2) * HWPLANE;
#pragma unroll
            for (int j = 0; j < 5; j++)
                pv0[j] = (gofs[j] >= 0) ? *reinterpret_cast<const float2*>(plane + gofs[j])
                                        : make_float2(0.0f, 0.0f);
        }
        if (more1) {
            const float* plane = inb + (size_t)(icBase + 3) * HWPLANE;
#pragma unroll
            for (int j = 0; j < 5; j++)
                pv1[j] = (gofs[j] >= 0) ? *reinterpret_cast<const float2*>(plane + gofs[j])
                                        : make_float2(0.0f, 0.0f);
        }

        // compute first channel of the stage
        compute_ic(s_in[curBase] + rowOff, icBase);

        // stage next plane 0 (data arrived under the 144-FMA span above)
        if (more0) {
            char* dst = (char*)s_in[nxtBase];
#pragma unroll
            for (int j = 0; j < 5; j++) {
                if (sy[j] >= 0) {
                    *reinterpret_cast<float*>(dst + sy[j]) = pv0[j].y;
                    if (!((skipx >> j) & 1))
                        *reinterpret_cast<float*>(dst + sy[j] - 4) = pv0[j].x;
                }
            }
        }

        // compute second channel of the stage
        if (icBase + 1 < IC)
            compute_ic(s_in[curBase + 1] + rowOff, icBase + 1);

        // stage next plane 1
        if (more1) {
            char* dst = (char*)s_in[nxtBase + 1];
#pragma unroll
            for (int j = 0; j < 5; j++) {
                if (sy[j] >= 0) {
                    *reinterpret_cast<float*>(dst + sy[j]) = pv1[j].y;
                    if (!((skipx >> j) & 1))
                        *reinterpret_cast<float*>(dst + sy[j] - 4) = pv1[j].x;
                }
            }
        }
        __syncthreads();
    }

    // ---- store ----
    const int x0 = tile_x + 2 * tX;
#pragma unroll
    for (int ocl = 0; ocl < 2; ocl++) {
        int oc = ocA + ocl;
        if (oc >= OC) break;
        size_t base = ((size_t)b * OC + oc) * HWPLANE;
#pragma unroll
        for (int dy = 0; dy < 8; dy++) {
            int y = tile_y + 8 * tY + dy;
            float f0, f1;
            unpack2(acc[ocl][dy], f0, f1);
            size_t idx = base + (size_t)y * WW + x0;
            if (RELU) { f0 = fmaxf(f0, 0.0f); f1 = fmaxf(f1, 0.0f); }
            if (RESID) {
                float2 rv = *reinterpret_cast<const float2*>(resid + idx);
                f0 += rv.x; f1 += rv.y;
            }
            *reinterpret_cast<float2*>(out + idx) = make_float2(f0, f1);
        }
    }
}

// ============================================================
// kernel_conv: softmax(|core|) over 225 taps + dynamic filter
// ============================================================
__global__ __launch_bounds__(256)
void kpn_apply_k(const float* __restrict__ core,
                 const float* __restrict__ data,
                 float* __restrict__ pred)
{
    __shared__ float s_data[3][30][32];

    const int tid = threadIdx.x;
    const int lx = tid & 15;
    const int ly = tid >> 4;
    const int tile_x = blockIdx.x * 16;
    const int tile_y = blockIdx.y * 16;
    const int b = blockIdx.z;

    for (int i = tid; i < 3 * 30 * 30; i += 256) {
        int c = i / 900;
        int r = (i - c * 900) / 30;
        int col = i - c * 900 - r * 30;
        int gy = tile_y - 7 + r;
        int gx = tile_x - 7 + col;
        float v = 0.0f;
        if (gy >= 0 && gy < HH && gx >= 0 && gx < WW)
            v = data[((size_t)b * 3 + c) * HWPLANE + gy * WW + gx];
        s_data[c][r][col] = v;
    }
    __syncthreads();

    const int y = tile_y + ly;
    const int x = tile_x + lx;
    const float* cb = core + (size_t)b * KK2 * HWPLANE + (size_t)y * WW + x;

    float S = 0.0f, P0 = 0.0f, P1 = 0.0f, P2 = 0.0f;

    for (int ki = 0; ki < KK; ki++) {
#pragma unroll
        for (int kj = 0; kj < KK; kj++) {
            float c = cb[(size_t)(ki * KK + kj) * HWPLANE];
            float w = __expf(fabsf(c));
            S += w;
            P0 += w * s_data[0][ly + ki][lx + kj];
            P1 += w * s_data[1][ly + ki][lx + kj];
            P2 += w * s_data[2][ly + ki][lx + kj];
        }
    }

    float inv = 1.0f / S;
    size_t o = (size_t)b * 3 * HWPLANE + (size_t)y * WW + x;
    pred[o]                = P0 * inv;
    pred[o + HWPLANE]      = P1 * inv;
    pred[o + 2 * HWPLANE]  = P2 * inv;
}

static float* sym_addr(const void* s)
{
    void* p = nullptr;
    cudaGetSymbolAddress(&p, s);
    return (float*)p;
}

extern "C" void kernel_launch(void* const* d_in, const int* in_sizes, int n_in,
                              void* d_out, int out_size)
{
    const float* dwe     = (const float*)d_in[0];
    const float* data    = (const float*)d_in[1];
    const float* w_first = (const float*)d_in[2];
    const float* b_first = (const float*)d_in[3];
    const float* w1a = (const float*)d_in[4];
    const float* b1a = (const float*)d_in[5];
    const float* w1b = (const float*)d_in[6];
    const float* b1b = (const float*)d_in[7];
    const float* w2a = (const float*)d_in[8];
    const float* b2a = (const float*)d_in[9];
    const float* w2b = (const float*)d_in[10];
    const float* b2b = (const float*)d_in[11];
    const float* w3a = (const float*)d_in[12];
    const float* b3a = (const float*)d_in[13];
    const float* w3b = (const float*)d_in[14];
    const float* b3b = (const float*)d_in[15];
    const float* w_out = (const float*)d_in[16];
    const float* b_out = (const float*)d_in[17];

    float* f0   = sym_addr(g_feat0);
    float* f1   = sym_addr(g_feat1);
    float* core = sym_addr(g_core);

    dim3 blk(256);
    dim3 grid64(WW / 32, HH / 64, BB * (NF / 4));       // 8,4,64
    const int ocGroupsOut = (KK2 + 3) / 4;              // 57
    dim3 gridOut(WW / 32, HH / 64, BB * ocGroupsOut);   // 8,4,228

    conv3x3_k<6, false, false><<<grid64, blk>>>(dwe, w_first, b_first, nullptr, f0, NF, NF / 4);

    conv3x3_k<64, true,  false><<<grid64, blk>>>(f0, w1a, b1a, nullptr, f1, NF, NF / 4);
    conv3x3_k<64, false, true ><<<grid64, blk>>>(f1, w1b, b1b, f0,      f0, NF, NF / 4);
    conv3x3_k<64, true,  false><<<grid64, blk>>>(f0, w2a, b2a, nullptr, f1, NF, NF / 4);
    conv3x3_k<64, false, true ><<<grid64, blk>>>(f1, w2b, b2b, f0,      f0, NF, NF / 4);
    conv3x3_k<64, true,  false><<<grid64, blk>>>(f0, w3a, b3a, nullptr, f1, NF, NF / 4);
    conv3x3_k<64, false, true ><<<grid64, blk>>>(f1, w3b, b3b, f0,      f0, NF, NF / 4);

    conv3x3_k<64, false, false><<<gridOut, blk>>>(f0, w_out, b_out, nullptr, core, KK2, ocGroupsOut);

    cudaMemcpyAsync(d_out, data, (size_t)BB * 3 * HWPLANE * sizeof(float),
                    cudaMemcpyDeviceToDevice, 0);

    dim3 gridK(WW / 16, HH / 16, BB);
    kpn_apply_k<<<gridK, blk>>>(core, data, (float*)d_out + (size_t)BB * 3 * HWPLANE);
}

// round 8
// speedup vs baseline: 1.0430x; 1.0003x over previous
#include <cuda_runtime.h>
#include <cstddef>

#define BB 4
#define HH 256
#define WW 256
#define HWPLANE (HH * WW)
#define NF 64
#define KK 15
#define KK2 (KK * KK)   // 225

__device__ float g_feat0[BB * NF * HWPLANE];
__device__ float g_feat1[BB * NF * HWPLANE];
__device__ float g_core [BB * KK2 * HWPLANE];

typedef unsigned long long u64;

__device__ __forceinline__ u64 pack2(float lo, float hi) {
    u64 r;
    asm("mov.b64 %0, {%1, %2};" : "=l"(r) : "f"(lo), "f"(hi));
    return r;
}
__device__ __forceinline__ void unpack2(u64 v, float& lo, float& hi) {
    asm("mov.b64 {%0, %1}, %2;" : "=f"(lo), "=f"(hi) : "l"(v));
}
__device__ __forceinline__ void fma2(u64& acc, u64 a, u64 b) {
    asm("fma.rn.f32x2 %0, %1, %2, %0;" : "+l"(acc) : "l"(a), "l"(b));
}

// ============================================================
// conv3x3 SAME, NCHW, fp32.
// Block: 256 threads, tile 32 wide x 64 tall, 4 out-channels.
// Thread: 2px (f32x2) x 8 rows x 2 oc = 32 outputs.
// 2 input channels per barrier stage (4 halo buffers); both
// next planes prefetched at stage start; weights via LDS.128.
// ============================================================
template<int IC, bool RELU, bool RESID>
__global__ __launch_bounds__(256, 2)
void conv3x3_k(const float* __restrict__ in,
               const float* __restrict__ wgt,
               const float* __restrict__ bias,
               const float* __restrict__ resid,
               float* __restrict__ out,
               int OC, int ocGroups)
{
    __shared__ float s_in[4][66 * 36];                 // 4 x 9.3KB
    __shared__ alignas(16) u64 s_w[IC * 40];           // [ic][ocl(4)][tap(10 padded)]

    const int tid  = threadIdx.x;
    const int tX   = tid & 15;
    const int tY   = (tid >> 4) & 7;
    const int half = tid >> 7;

    const int tile_x = blockIdx.x * 32;
    const int tile_y = blockIdx.y * 64;
    const int zb = blockIdx.z;
    const int b   = zb / ocGroups;
    const int g   = zb - b * ocGroups;
    const int oc0 = g * 4;
    const int ocA = oc0 + half * 2;

    // ---- weights into smem: duplicated pairs, lane padded to 10 ----
    for (int i = tid; i < IC * 40; i += 256) {
        int ic  = i / 40;
        int r   = i - ic * 40;
        int ocl = r / 10;
        int tap = r - ocl * 10;
        int oc  = oc0 + ocl;
        float v = (oc < OC && tap < 9) ? wgt[((size_t)oc * IC + ic) * 9 + tap] : 0.0f;
        s_w[i] = pack2(v, v);
    }

    float bz[2];
#pragma unroll
    for (int o = 0; o < 2; o++)
        bz[o] = (ocA + o < OC) ? bias[ocA + o] : 0.0f;

    const float* inb = in + (size_t)b * IC * HWPLANE;

    // ---- hoisted halo addressing (66 rows x 18 float2 pairs) ----
    // smem col c' = gx - (tile_x-1); pair k: v.x -> c'=2k-1 (skip k==0), v.y -> c'=2k
    int sy[5], gofs[5];
    unsigned skipx = 0;
#pragma unroll
    for (int j = 0; j < 5; j++) {
        int i = tid + j * 256;
        int row = i / 18, pc = i - row * 18;
        bool slot = (i < 66 * 18);
        int gy = tile_y - 1 + row;
        int gx0 = tile_x - 2 + 2 * pc;
        bool v = slot && gy >= 0 && gy < HH && gx0 >= 0 && gx0 < WW;
        gofs[j] = v ? (gy * WW + gx0) : -1;
        sy[j]   = slot ? (row * 36 + 2 * pc) * 4 : -1;
        if (pc == 0) skipx |= (1u << j);
    }

    // ---- stage channels 0,1 into buffers 0,1 ----
#pragma unroll
    for (int c = 0; c < 2 && c < IC; c++) {
        const float* plane = inb + (size_t)c * HWPLANE;
        float2 pv[5];
#pragma unroll
        for (int j = 0; j < 5; j++)
            pv[j] = (gofs[j] >= 0) ? *reinterpret_cast<const float2*>(plane + gofs[j])
                                   : make_float2(0.0f, 0.0f);
        char* dst = (char*)s_in[c];
#pragma unroll
        for (int j = 0; j < 5; j++) {
            if (sy[j] >= 0) {
                *reinterpret_cast<float*>(dst + sy[j]) = pv[j].y;
                if (!((skipx >> j) & 1))
                    *reinterpret_cast<float*>(dst + sy[j] - 4) = pv[j].x;
            }
        }
    }
    __syncthreads();

    u64 acc[2][8];
#pragma unroll
    for (int o = 0; o < 2; o++) {
        u64 bb2 = pack2(bz[o], bz[o]);
#pragma unroll
        for (int r = 0; r < 8; r++) acc[o][r] = bb2;
    }

    const int rowOff = (8 * tY) * 36 + 2 * tX;

    // compute one input channel from buffer S with weights for ic
    auto compute_ic = [&](const float* S, int ic) {
        // weights: 4 LDS.128 + 1 LDS.64 per oc
        u64 w[2][9];
        {
            const u64* Wc = &s_w[ic * 40 + half * 20];
#pragma unroll
            for (int ocl = 0; ocl < 2; ocl++) {
#pragma unroll
                for (int q = 0; q < 4; q++) {
                    ulonglong2 t = *reinterpret_cast<const ulonglong2*>(Wc + ocl * 10 + 2 * q);
                    w[ocl][2 * q] = t.x; w[ocl][2 * q + 1] = t.y;
                }
                w[ocl][8] = Wc[ocl * 10 + 8];
            }
        }
        u64 p[3][3];
#pragma unroll
        for (int h = 0; h < 3; h++) {
            const float* row = S + h * 36;
            u64 A = *reinterpret_cast<const u64*>(row);
            u64 B = *reinterpret_cast<const u64*>(row + 2);
            float a0, a1, b0, b1;
            unpack2(A, a0, a1); unpack2(B, b0, b1);
            p[h][0] = A; p[h][1] = pack2(a1, b0); p[h][2] = B;
        }
#pragma unroll
        for (int r = 0; r < 8; r++) {
#pragma unroll
            for (int ki = 0; ki < 3; ki++) {
                const int slot = (r + ki) % 3;
#pragma unroll
                for (int kj = 0; kj < 3; kj++) {
                    fma2(acc[0][r], p[slot][kj], w[0][ki * 3 + kj]);
                    fma2(acc[1][r], p[slot][kj], w[1][ki * 3 + kj]);
                }
            }
            if (r < 7) {
                const int slot = r % 3;
                const float* row = S + (r + 3) * 36;
                u64 A = *reinterpret_cast<const u64*>(row);
                u64 B = *reinterpret_cast<const u64*>(row + 2);
                float a0, a1, b0, b1;
                unpack2(A, a0, a1); unpack2(B, b0, b1);
                p[slot][0] = A; p[slot][1] = pack2(a1, b0); p[slot][2] = B;
            }
        }
    };

    const int nStages = (IC + 1) / 2;
#pragma unroll 1
    for (int s = 0; s < nStages; ++s) {
        const int icBase  = 2 * s;
        const int curBase = (s & 1) * 2;
        const int nxtBase = ((s + 1) & 1) * 2;

        // prefetch both planes of the next stage (independent LDGs, MLP=10)
        float2 pv0[5], pv1[5];
        const bool more0 = (icBase + 2 < IC);
        const bool more1 = (icBase + 3 < IC);
        if (more0) {
            const float* plane = inb + (size_t)(icBase + 2) * HWPLANE;
#pragma unroll
            for (int j = 0; j < 5; j++)
                pv0[j] = (gofs[j] >= 0) ? *reinterpret_cast<const float2*>(plane + gofs[j])
                                        : make_float2(0.0f, 0.0f);
        }
        if (more1) {
            const float* plane = inb + (size_t)(icBase + 3) * HWPLANE;
#pragma unroll
            for (int j = 0; j < 5; j++)
                pv1[j] = (gofs[j] >= 0) ? *reinterpret_cast<const float2*>(plane + gofs[j])
                                        : make_float2(0.0f, 0.0f);
        }

        // compute first channel of the stage
        compute_ic(s_in[curBase] + rowOff, icBase);

        // stage next plane 0 (data arrived under the 144-FMA span above)
        if (more0) {
            char* dst = (char*)s_in[nxtBase];
#pragma unroll
            for (int j = 0; j < 5; j++) {
                if (sy[j] >= 0) {
                    *reinterpret_cast<float*>(dst + sy[j]) = pv0[j].y;
                    if (!((skipx >> j) & 1))
                        *reinterpret_cast<float*>(dst + sy[j] - 4) = pv0[j].x;
                }
            }
        }

        // compute second channel of the stage
        if (icBase + 1 < IC)
            compute_ic(s_in[curBase + 1] + rowOff, icBase + 1);

        // stage next plane 1
        if (more1) {
            char* dst = (char*)s_in[nxtBase + 1];
#pragma unroll
            for (int j = 0; j < 5; j++) {
                if (sy[j] >= 0) {
                    *reinterpret_cast<float*>(dst + sy[j]) = pv1[j].y;
                    if (!((skipx >> j) & 1))
                        *reinterpret_cast<float*>(dst + sy[j] - 4) = pv1[j].x;
                }
            }
        }
        __syncthreads();
    }

    // ---- store ----
    const int x0 = tile_x + 2 * tX;
#pragma unroll
    for (int ocl = 0; ocl < 2; ocl++) {
        int oc = ocA + ocl;
        if (oc >= OC) break;
        size_t base = ((size_t)b * OC + oc) * HWPLANE;
#pragma unroll
        for (int dy = 0; dy < 8; dy++) {
            int y = tile_y + 8 * tY + dy;
            float f0, f1;
            unpack2(acc[ocl][dy], f0, f1);
            size_t idx = base + (size_t)y * WW + x0;
            if (RELU) { f0 = fmaxf(f0, 0.0f); f1 = fmaxf(f1, 0.0f); }
            if (RESID) {
                float2 rv = *reinterpret_cast<const float2*>(resid + idx);
                f0 += rv.x; f1 += rv.y;
            }
            *reinterpret_cast<float2*>(out + idx) = make_float2(f0, f1);
        }
    }
}

// ============================================================
// kernel_conv: softmax(|core|) over 225 taps + dynamic filter
// ============================================================
__global__ __launch_bounds__(256)
void kpn_apply_k(const float* __restrict__ core,
                 const float* __restrict__ data,
                 float* __restrict__ pred)
{
    __shared__ float s_data[3][30][32];

    const int tid = threadIdx.x;
    const int lx = tid & 15;
    const int ly = tid >> 4;
    const int tile_x = blockIdx.x * 16;
    const int tile_y = blockIdx.y * 16;
    const int b = blockIdx.z;

    for (int i = tid; i < 3 * 30 * 30; i += 256) {
        int c = i / 900;
        int r = (i - c * 900) / 30;
        int col = i - c * 900 - r * 30;
        int gy = tile_y - 7 + r;
        int gx = tile_x - 7 + col;
        float v = 0.0f;
        if (gy >= 0 && gy < HH && gx >= 0 && gx < WW)
            v = data[((size_t)b * 3 + c) * HWPLANE + gy * WW + gx];
        s_data[c][r][col] = v;
    }
    __syncthreads();

    const int y = tile_y + ly;
    const int x = tile_x + lx;
    const float* cb = core + (size_t)b * KK2 * HWPLANE + (size_t)y * WW + x;

    float S = 0.0f, P0 = 0.0f, P1 = 0.0f, P2 = 0.0f;

    for (int ki = 0; ki < KK; ki++) {
#pragma unroll
        for (int kj = 0; kj < KK; kj++) {
            float c = cb[(size_t)(ki * KK + kj) * HWPLANE];
            float w = __expf(fabsf(c));
            S += w;
            P0 += w * s_data[0][ly + ki][lx + kj];
            P1 += w * s_data[1][ly + ki][lx + kj];
            P2 += w * s_data[2][ly + ki][lx + kj];
        }
    }

    float inv = 1.0f / S;
    size_t o = (size_t)b * 3 * HWPLANE + (size_t)y * WW + x;
    pred[o]                = P0 * inv;
    pred[o + HWPLANE]      = P1 * inv;
    pred[o + 2 * HWPLANE]  = P2 * inv;
}

static float* sym_addr(const void* s)
{
    void* p = nullptr;
    cudaGetSymbolAddress(&p, s);
    return (float*)p;
}

extern "C" void kernel_launch(void* const* d_in, const int* in_sizes, int n_in,
                              void* d_out, int out_size)
{
    const float* dwe     = (const float*)d_in[0];
    const float* data    = (const float*)d_in[1];
    const float* w_first = (const float*)d_in[2];
    const float* b_first = (const float*)d_in[3];
    const float* w1a = (const float*)d_in[4];
    const float* b1a = (const float*)d_in[5];
    const float* w1b = (const float*)d_in[6];
    const float* b1b = (const float*)d_in[7];
    const float* w2a = (const float*)d_in[8];
    const float* b2a = (const float*)d_in[9];
    const float* w2b = (const float*)d_in[10];
    const float* b2b = (const float*)d_in[11];
    const float* w3a = (const float*)d_in[12];
    const float* b3a = (const float*)d_in[13];
    const float* w3b = (const float*)d_in[14];
    const float* b3b = (const float*)d_in[15];
    const float* w_out = (const float*)d_in[16];
    const float* b_out = (const float*)d_in[17];

    float* f0   = sym_addr(g_feat0);
    float* f1   = sym_addr(g_feat1);
    float* core = sym_addr(g_core);

    dim3 blk(256);
    dim3 grid64(WW / 32, HH / 64, BB * (NF / 4));       // 8,4,64
    const int ocGroupsOut = (KK2 + 3) / 4;              // 57
    dim3 gridOut(WW / 32, HH / 64, BB * ocGroupsOut);   // 8,4,228

    conv3x3_k<6, false, false><<<grid64, blk>>>(dwe, w_first, b_first, nullptr, f0, NF, NF / 4);

    conv3x3_k<64, true,  false><<<grid64, blk>>>(f0, w1a, b1a, nullptr, f1, NF, NF / 4);
    conv3x3_k<64, false, true ><<<grid64, blk>>>(f1, w1b, b1b, f0,      f0, NF, NF / 4);
    conv3x3_k<64, true,  false><<<grid64, blk>>>(f0, w2a, b2a, nullptr, f1, NF, NF / 4);
    conv3x3_k<64, false, true ><<<grid64, blk>>>(f1, w2b, b2b, f0,      f0, NF, NF / 4);
    conv3x3_k<64, true,  false><<<grid64, blk>>>(f0, w3a, b3a, nullptr, f1, NF, NF / 4);
    conv3x3_k<64, false, true ><<<grid64, blk>>>(f1, w3b, b3b, f0,      f0, NF, NF / 4);

    conv3x3_k<64, false, false><<<gridOut, blk>>>(f0, w_out, b_out, nullptr, core, KK2, ocGroupsOut);

    cudaMemcpyAsync(d_out, data, (size_t)BB * 3 * HWPLANE * sizeof(float),
                    cudaMemcpyDeviceToDevice, 0);

    dim3 gridK(WW / 16, HH / 16, BB);
    kpn_apply_k<<<gridK, blk>>>(core, data, (float*)d_out + (size_t)BB * 3 * HWPLANE);
}

// round 10
// speedup vs baseline: 2.0690x; 1.9837x over previous
#include <cuda_runtime.h>
#include <cuda_bf16.h>
#include <cstdint>
#include <cstddef>

typedef unsigned int u32;
typedef unsigned long long u64;

#define BB 4
#define HH 256
#define WW 256
#define HWP (HH * WW)
#define NPIX (BB * HWP)
#define CPAD 228

// ---------------- device global scratch ----------------
__device__ __nv_bfloat16 g_p6h[(size_t)NPIX * 64], g_p6l[(size_t)NPIX * 64];
__device__ __nv_bfloat16 g_pAh[(size_t)NPIX * 64], g_pAl[(size_t)NPIX * 64];
__device__ __nv_bfloat16 g_pBh[(size_t)NPIX * 64], g_pBl[(size_t)NPIX * 64];
__device__ __nv_bfloat16 g_pCh[(size_t)NPIX * 64], g_pCl[(size_t)NPIX * 64];
__device__ float         g_core2[(size_t)NPIX * CPAD];
__device__ u32           g_wfrag[377856];

#define SWZ128(o) ((o) ^ (((o) >> 3) & 0x70))

__device__ __forceinline__ u32 smem_u32(const void* p) {
    u32 a;
    asm("{ .reg .u64 t; cvta.to.shared.u64 t, %1; cvt.u32.u64 %0, t; }" : "=r"(a) : "l"(p));
    return a;
}

#define LDSM4(r, a) asm volatile( \
    "ldmatrix.sync.aligned.m8n8.x4.shared.b16 {%0,%1,%2,%3}, [%4];" \
    : "=r"((r)[0]), "=r"((r)[1]), "=r"((r)[2]), "=r"((r)[3]) : "r"(a))

#define MMA16816(d, a, b0v, b1v) asm volatile( \
    "mma.sync.aligned.m16n8k16.row.col.f32.bf16.bf16.f32 " \
    "{%0,%1,%2,%3}, {%4,%5,%6,%7}, {%8,%9}, {%0,%1,%2,%3};" \
    : "+f"((d)[0]), "+f"((d)[1]), "+f"((d)[2]), "+f"((d)[3]) \
    : "r"((a)[0]), "r"((a)[1]), "r"((a)[2]), "r"((a)[3]), "r"(b0v), "r"(b1v))

// ============================================================
// pack6: data_with_est [B,6,H,W] fp32 -> NHWC-64 bf16 hi/lo
// ============================================================
__global__ __launch_bounds__(256) void pack6_k(const float* __restrict__ in)
{
    int g = blockIdx.x * 256 + threadIdx.x;
    int b = g >> 16, p = g & 65535;
    alignas(16) __nv_bfloat16 h[64], l[64];
#pragma unroll
    for (int c = 0; c < 64; c++) { h[c] = __float2bfloat16(0.f); l[c] = __float2bfloat16(0.f); }
#pragma unroll
    for (int c = 0; c < 6; c++) {
        float v = in[((size_t)b * 6 + c) * HWP + p];
        __nv_bfloat16 hi = __float2bfloat16(v);
        h[c] = hi;
        l[c] = __float2bfloat16(v - __bfloat162float(hi));
    }
    uint4* dh = reinterpret_cast<uint4*>(g_p6h + (size_t)g * 64);
    uint4* dl = reinterpret_cast<uint4*>(g_p6l + (size_t)g * 64);
    const uint4* sh = reinterpret_cast<const uint4*>(h);
    const uint4* sl = reinterpret_cast<const uint4*>(l);
#pragma unroll
    for (int i = 0; i < 8; i++) { dh[i] = sh[i]; dl[i] = sl[i]; }
}

// ============================================================
// wprep2: OIHW fp32 -> per-lane mma B-fragments (bf16x2 in u32)
// index = ((((tap*2+plane)*KS + q)*NT + ntile)*64 + lane*2 + reg)
// value: {B[k0][n], B[k0+1][n]}, k0 = q*16 + (lane%4)*2 + reg*8,
//        n = ntile*8 + lane/4 ; B[k][n] = W[oc=n][ic=k]
// ============================================================
__global__ void wprep2_k(const float* __restrict__ w, int OCs, int ICs,
                         int KS, int NT, int dstoff)
{
    int n = 9 * 2 * KS * NT * 64;
    for (int i = blockIdx.x * blockDim.x + threadIdx.x; i < n; i += gridDim.x * blockDim.x) {
        int rem = i;
        int tap   = rem / (2 * KS * NT * 64); rem -= tap * (2 * KS * NT * 64);
        int plane = rem / (KS * NT * 64);     rem -= plane * (KS * NT * 64);
        int q     = rem / (NT * 64);          rem -= q * (NT * 64);
        int ntile = rem / 64;                 rem -= ntile * 64;
        int lane = rem >> 1, reg = rem & 1;
        int nn = ntile * 8 + (lane >> 2);
        int k0 = q * 16 + (lane & 3) * 2 + reg * 8;
        u32 outv = 0;
#pragma unroll
        for (int e = 0; e < 2; e++) {
            int k = k0 + e;
            float v = (nn < OCs && k < ICs) ? w[((size_t)nn * ICs + k) * 9 + tap] : 0.f;
            __nv_bfloat16 hb = __float2bfloat16(v);
            __nv_bfloat16 ob = (plane == 0) ? hb
                               : __float2bfloat16(v - __bfloat162float(hb));
            unsigned short bits = *reinterpret_cast<unsigned short*>(&ob);
            outv |= ((u32)bits) << (16 * e);
        }
        g_wfrag[dstoff + i] = outv;
    }
}

// ============================================================
// convM: 3x3 conv as 9-tap implicit GEMM on mma.sync (HMMA).
// Block: 256 thr (8 warps, 4Mx2N), tile = 128 px strip x 64 oc.
// A: [128px][64ic] bf16 hi/lo, swizzled smem, double-buffered per tap.
// 3-pass hi/lo: AhBh + AhBl + AlBh into fp32 accumulators.
// ============================================================
template<int KS, int NT, bool RELU, bool RESID, bool OUTM>
__global__ __launch_bounds__(256, 1)
void convM_k(const __nv_bfloat16* __restrict__ inh, const __nv_bfloat16* __restrict__ inl,
             const __nv_bfloat16* __restrict__ rh,  const __nv_bfloat16* __restrict__ rl,
             __nv_bfloat16* __restrict__ outh, __nv_bfloat16* __restrict__ outl,
             float* __restrict__ outf, const float* __restrict__ bias,
             const u32* __restrict__ bfrag)
{
    extern __shared__ char smem[];
    const u32 sbase = smem_u32(smem);
    const int tid   = threadIdx.x;
    const int lane  = tid & 31;
    const int warp  = tid >> 5;
    const int warpM = warp & 3, warpN = warp >> 2;

    const int x0 = blockIdx.x * 128;
    const int y  = blockIdx.y;
    int b = blockIdx.z, chunk = 0;
    if (OUTM) { chunk = b & 3; b >>= 2; }

    // staging constants (4 uint4 per plane per thread)
    const int rowB = tid >> 3;
    const int cc   = tid & 7;
    u32 soff[4];
    int xb[4];
#pragma unroll
    for (int j = 0; j < 4; j++) {
        int row = rowB + 32 * j;
        soff[j] = SWZ128((u32)(row * 128 + cc * 16));
        xb[j] = x0 + row - 1;
    }
    const size_t bbase = (size_t)b * HWP;

    float acc[2][4][4];
#pragma unroll
    for (int mt = 0; mt < 2; mt++)
#pragma unroll
        for (int nt = 0; nt < 4; nt++)
#pragma unroll
            for (int e = 0; e < 4; e++) acc[mt][nt][e] = 0.f;

    uint4 ph[4], pl[4];
    auto fetch = [&](int t) {
        int dy = t / 3, dx = t - 3 * dy;
        int gy = y + dy - 1;
        bool yok = (unsigned)gy < HH;
        size_t rb = bbase + (size_t)gy * WW;
#pragma unroll
        for (int j = 0; j < 4; j++) {
            int xt = xb[j] + dx;
            bool ok = yok && (unsigned)xt < WW;
            size_t gi = (rb + xt) * 64 + cc * 8;
            ph[j] = ok ? *reinterpret_cast<const uint4*>(inh + gi) : make_uint4(0, 0, 0, 0);
            pl[j] = ok ? *reinterpret_cast<const uint4*>(inl + gi) : make_uint4(0, 0, 0, 0);
        }
    };
    auto sts = [&](int bf) {
#pragma unroll
        for (int j = 0; j < 4; j++) {
            *reinterpret_cast<uint4*>(smem + bf * 32768 + soff[j])         = ph[j];
            *reinterpret_cast<uint4*>(smem + bf * 32768 + 16384 + soff[j]) = pl[j];
        }
    };

    fetch(0);
    sts(0);
    __syncthreads();

    const int r16 = lane & 15, tk = lane >> 4;

#pragma unroll 1
    for (int t = 0; t < 9; t++) {
        const int bf = t & 1;
        if (t < 8) fetch(t + 1);

        const u32 aBaseH = sbase + bf * 32768;
        const u32 aBaseL = aBaseH + 16384;

#pragma unroll
        for (int q = 0; q < KS; q++) {
            u32 ah[2][4], al[2][4];
#pragma unroll
            for (int mt = 0; mt < 2; mt++) {
                int P = warpM * 32 + mt * 16;
                u32 off = SWZ128((u32)((P + r16) * 128 + q * 32 + tk * 16));
                LDSM4(ah[mt], aBaseH + off);
                LDSM4(al[mt], aBaseL + off);
            }
#pragma unroll
            for (int nt = 0; nt < 4; nt++) {
                int ntg = chunk * 8 + warpN * 4 + nt;
                const u32* bpH = bfrag + (((size_t)(t * 2 + 0) * KS + q) * NT + ntg) * 64 + lane * 2;
                const u32* bpL = bfrag + (((size_t)(t * 2 + 1) * KS + q) * NT + ntg) * 64 + lane * 2;
                u32 bh0 = bpH[0], bh1 = bpH[1];
                u32 bl0 = bpL[0], bl1 = bpL[1];
#pragma unroll
                for (int mt = 0; mt < 2; mt++) {
                    MMA16816(acc[mt][nt], ah[mt], bh0, bh1);
                    MMA16816(acc[mt][nt], ah[mt], bl0, bl1);
                    MMA16816(acc[mt][nt], al[mt], bh0, bh1);
                }
            }
        }

        if (t < 8) sts(bf ^ 1);
        __syncthreads();
    }

    // ---- epilogue ----
#pragma unroll
    for (int nt = 0; nt < 4; nt++) {
        int oc = (OUTM ? chunk * 64 : 0) + warpN * 32 + nt * 8 + (lane & 3) * 2;
        float bz0, bz1;
        if (OUTM) {
            bz0 = (oc < 225) ? bias[oc] : 0.f;
            bz1 = (oc + 1 < 225) ? bias[oc + 1] : 0.f;
        } else {
            bz0 = bias[oc]; bz1 = bias[oc + 1];
        }
#pragma unroll
        for (int mt = 0; mt < 2; mt++) {
#pragma unroll
            for (int rr = 0; rr < 2; rr++) {
                int m = warpM * 32 + mt * 16 + (lane >> 2) + rr * 8;
                size_t pb = bbase + (size_t)y * WW + x0 + m;
                float v0 = acc[mt][nt][rr * 2 + 0] + bz0;
                float v1 = acc[mt][nt][rr * 2 + 1] + bz1;
                if (OUTM) {
                    if (oc < 228)
                        *reinterpret_cast<float2*>(outf + pb * CPAD + oc) = make_float2(v0, v1);
                } else {
                    size_t ei = pb * 64 + oc;
                    if (RESID) {
                        u32 hh = *reinterpret_cast<const u32*>(rh + ei);
                        u32 ll = *reinterpret_cast<const u32*>(rl + ei);
                        __nv_bfloat162 h2 = *reinterpret_cast<__nv_bfloat162*>(&hh);
                        __nv_bfloat162 l2 = *reinterpret_cast<__nv_bfloat162*>(&ll);
                        v0 += __bfloat162float(h2.x) + __bfloat162float(l2.x);
                        v1 += __bfloat162float(h2.y) + __bfloat162float(l2.y);
                    }
                    if (RELU) { v0 = fmaxf(v0, 0.f); v1 = fmaxf(v1, 0.f); }
                    __nv_bfloat16 h0 = __float2bfloat16(v0);
                    __nv_bfloat16 h1 = __float2bfloat16(v1);
                    __nv_bfloat16 l0 = __float2bfloat16(v0 - __bfloat162float(h0));
                    __nv_bfloat16 l1 = __float2bfloat16(v1 - __bfloat162float(h1));
                    __nv_bfloat162 hv; hv.x = h0; hv.y = h1;
                    __nv_bfloat162 lv; lv.x = l0; lv.y = l1;
                    *reinterpret_cast<__nv_bfloat162*>(outh + ei) = hv;
                    *reinterpret_cast<__nv_bfloat162*>(outl + ei) = lv;
                }
            }
        }
    }
}

// ============================================================
// kpn: per-pixel softmax(|core|) over 225 taps + 15x15 filter.
// core2 tap-contiguous [b][y][x][228].
// ============================================================
__global__ __launch_bounds__(128)
void kpn2_k(const float* __restrict__ data, float* __restrict__ pred)
{
    __shared__ float sd[3][15][144];
    const int tid = threadIdx.x;
    const int x0 = blockIdx.x * 128;
    const int y  = blockIdx.y;
    const int b  = blockIdx.z;

    for (int i = tid; i < 3 * 15 * 142; i += 128) {
        int c = i / (15 * 142);
        int r = (i - c * 15 * 142) / 142;
        int q = i - c * 15 * 142 - r * 142;
        int gy = y - 7 + r, gx = x0 - 7 + q;
        float v = 0.0f;
        if ((unsigned)gy < HH && (unsigned)gx < WW)
            v = data[((size_t)(b * 3 + c)) * HWP + gy * WW + gx];
        sd[c][r][q] = v;
    }
    __syncthreads();

    const int px = tid;
    const float4* cr = reinterpret_cast<const float4*>(
        g_core2 + ((size_t)b * HWP + (size_t)y * WW + x0 + px) * CPAD);

    float S = 0.f, P0 = 0.f, P1 = 0.f, P2 = 0.f;
    int ki = 0, kj = 0;
#pragma unroll 1
    for (int q = 0; q < 57; q++) {
        float4 f = cr[q];
        float fv[4] = {f.x, f.y, f.z, f.w};
#pragma unroll
        for (int s = 0; s < 4; s++) {
            int t = q * 4 + s;
            if (t < 225) {
                float w = __expf(fabsf(fv[s]));
                S  += w;
                P0 += w * sd[0][ki][px + kj];
                P1 += w * sd[1][ki][px + kj];
                P2 += w * sd[2][ki][px + kj];
                if (++kj == 15) { kj = 0; ki++; }
            }
        }
    }
    float inv = 1.0f / S;
    size_t o = (size_t)b * 3 * HWP + (size_t)y * WW + x0 + px;
    pred[o]           = P0 * inv;
    pred[o + HWP]     = P1 * inv;
    pred[o + 2 * HWP] = P2 * inv;
}

// ============================================================
// launch
// ============================================================
template<typename T>
static T* sym(const void* s) { void* p = nullptr; cudaGetSymbolAddress(&p, s); return (T*)p; }

extern "C" void kernel_launch(void* const* d_in, const int* in_sizes, int n_in,
                              void* d_out, int out_size)
{
    const float* dwe     = (const float*)d_in[0];
    const float* data    = (const float*)d_in[1];
    const float* w_first = (const float*)d_in[2];
    const float* b_first = (const float*)d_in[3];
    const float* w1a = (const float*)d_in[4];  const float* b1a = (const float*)d_in[5];
    const float* w1b = (const float*)d_in[6];  const float* b1b = (const float*)d_in[7];
    const float* w2a = (const float*)d_in[8];  const float* b2a = (const float*)d_in[9];
    const float* w2b = (const float*)d_in[10]; const float* b2b = (const float*)d_in[11];
    const float* w3a = (const float*)d_in[12]; const float* b3a = (const float*)d_in[13];
    const float* w3b = (const float*)d_in[14]; const float* b3b = (const float*)d_in[15];
    const float* w_out = (const float*)d_in[16]; const float* b_out = (const float*)d_in[17];

    __nv_bfloat16* p6h = sym<__nv_bfloat16>(g_p6h); __nv_bfloat16* p6l = sym<__nv_bfloat16>(g_p6l);
    __nv_bfloat16* pAh = sym<__nv_bfloat16>(g_pAh); __nv_bfloat16* pAl = sym<__nv_bfloat16>(g_pAl);
    __nv_bfloat16* pBh = sym<__nv_bfloat16>(g_pBh); __nv_bfloat16* pBl = sym<__nv_bfloat16>(g_pBl);
    __nv_bfloat16* pCh = sym<__nv_bfloat16>(g_pCh); __nv_bfloat16* pCl = sym<__nv_bfloat16>(g_pCl);
    float* core2 = sym<float>(g_core2);
    const u32* wf = sym<u32>(g_wfrag);

    static bool once = false;
    if (!once) {
        cudaFuncSetAttribute(convM_k<1, 8, false, false, false>, cudaFuncAttributeMaxDynamicSharedMemorySize, 65536);
        cudaFuncSetAttribute(convM_k<4, 8, true,  false, false>, cudaFuncAttributeMaxDynamicSharedMemorySize, 65536);
        cudaFuncSetAttribute(convM_k<4, 8, false, true,  false>, cudaFuncAttributeMaxDynamicSharedMemorySize, 65536);
        cudaFuncSetAttribute(convM_k<4, 32, false, false, true>, cudaFuncAttributeMaxDynamicSharedMemorySize, 65536);
        once = true;
    }

    pack6_k<<<NPIX / 256, 256>>>(dwe);
    wprep2_k<<<96, 256>>>(w_first, 64, 6, 1, 8, 0);
    wprep2_k<<<96, 256>>>(w1a, 64, 64, 4, 8, 9216);
    wprep2_k<<<96, 256>>>(w1b, 64, 64, 4, 8, 46080);
    wprep2_k<<<96, 256>>>(w2a, 64, 64, 4, 8, 82944);
    wprep2_k<<<96, 256>>>(w2b, 64, 64, 4, 8, 119808);
    wprep2_k<<<96, 256>>>(w3a, 64, 64, 4, 8, 156672);
    wprep2_k<<<96, 256>>>(w3b, 64, 64, 4, 8, 193536);
    wprep2_k<<<288, 256>>>(w_out, 225, 64, 4, 32, 230400);

    dim3 grid(2, 256, 4), blk(256);
    convM_k<1, 8, false, false, false><<<grid, blk, 65536>>>(p6h, p6l, nullptr, nullptr, pAh, pAl, nullptr, b_first, wf + 0);
    convM_k<4, 8, true,  false, false><<<grid, blk, 65536>>>(pAh, pAl, nullptr, nullptr, pBh, pBl, nullptr, b1a, wf + 9216);
    convM_k<4, 8, false, true,  false><<<grid, blk, 65536>>>(pBh, pBl, pAh, pAl, pCh, pCl, nullptr, b1b, wf + 46080);
    convM_k<4, 8, true,  false, false><<<grid, blk, 65536>>>(pCh, pCl, nullptr, nullptr, pBh, pBl, nullptr, b2a, wf + 82944);
    convM_k<4, 8, false, true,  false><<<grid, blk, 65536>>>(pBh, pBl, pCh, pCl, pAh, pAl, nullptr, b2b, wf + 119808);
    convM_k<4, 8, true,  false, false><<<grid, blk, 65536>>>(pAh, pAl, nullptr, nullptr, pBh, pBl, nullptr, b3a, wf + 156672);
    convM_k<4, 8, false, true,  false><<<grid, blk, 65536>>>(pBh, pBl, pAh, pAl, pCh, pCl, nullptr, b3b, wf + 193536);

    dim3 gridO(2, 256, 16);
    convM_k<4, 32, false, false, true><<<gridO, blk, 65536>>>(pCh, pCl, nullptr, nullptr, nullptr, nullptr, core2, b_out, wf + 230400);

    cudaMemcpyAsync(d_out, data, (size_t)BB * 3 * HWP * sizeof(float),
                    cudaMemcpyDeviceToDevice, 0);

    kpn2_k<<<dim3(2, 256, 4), 128>>>(data, (float*)d_out + (size_t)BB * 3 * HWP);
}

// round 11
// speedup vs baseline: 3.1702x; 1.5322x over previous
#include <cuda_runtime.h>
#include <cuda_bf16.h>
#include <cstdint>
#include <cstddef>

typedef unsigned int u32;
typedef unsigned long long u64;

#define BB 4
#define HH 256
#define WW 256
#define HWP (HH * WW)
#define NPIX (BB * HWP)
#define CPAD 228

// ---------------- device global scratch ----------------
__device__ __nv_bfloat16 g_p6h[(size_t)NPIX * 64], g_p6l[(size_t)NPIX * 64];
__device__ __nv_bfloat16 g_pAh[(size_t)NPIX * 64], g_pAl[(size_t)NPIX * 64];
__device__ __nv_bfloat16 g_pBh[(size_t)NPIX * 64], g_pBl[(size_t)NPIX * 64];
__device__ __nv_bfloat16 g_pCh[(size_t)NPIX * 64], g_pCl[(size_t)NPIX * 64];
__device__ float         g_core2[(size_t)NPIX * CPAD];
__device__ u32           g_wfrag[377856];

#define SWZ128(o) ((o) ^ (((o) >> 3) & 0x70))

__device__ __forceinline__ u32 smem_u32(const void* p) {
    u32 a;
    asm("{ .reg .u64 t; cvta.to.shared.u64 t, %1; cvt.u32.u64 %0, t; }" : "=r"(a) : "l"(p));
    return a;
}

#define LDSM4(r, a) asm volatile( \
    "ldmatrix.sync.aligned.m8n8.x4.shared.b16 {%0,%1,%2,%3}, [%4];" \
    : "=r"((r)[0]), "=r"((r)[1]), "=r"((r)[2]), "=r"((r)[3]) : "r"(a))

#define MMA16816(d, a, b0v, b1v) asm volatile( \
    "mma.sync.aligned.m16n8k16.row.col.f32.bf16.bf16.f32 " \
    "{%0,%1,%2,%3}, {%4,%5,%6,%7}, {%8,%9}, {%0,%1,%2,%3};" \
    : "+f"((d)[0]), "+f"((d)[1]), "+f"((d)[2]), "+f"((d)[3]) \
    : "r"((a)[0]), "r"((a)[1]), "r"((a)[2]), "r"((a)[3]), "r"(b0v), "r"(b1v))

// smem plane geometry: 3 planes (dy), each hi+lo; rows 0..129 <-> gx = x0-1..x0+128
#define PLANE_STRIDE 34816          // 34 * 1024 (keeps swizzle base-aligned)
#define LO_OFF       17408          // 17 * 1024
#define SMEM_BYTES   (3 * PLANE_STRIDE)   // 104448

// ============================================================
// pack6: data_with_est [B,6,H,W] fp32 -> NHWC-64 bf16 hi/lo
// ============================================================
__global__ __launch_bounds__(256) void pack6_k(const float* __restrict__ in)
{
    int g = blockIdx.x * 256 + threadIdx.x;
    int b = g >> 16, p = g & 65535;
    alignas(16) __nv_bfloat16 h[64], l[64];
#pragma unroll
    for (int c = 0; c < 64; c++) { h[c] = __float2bfloat16(0.f); l[c] = __float2bfloat16(0.f); }
#pragma unroll
    for (int c = 0; c < 6; c++) {
        float v = in[((size_t)b * 6 + c) * HWP + p];
        __nv_bfloat16 hi = __float2bfloat16(v);
        h[c] = hi;
        l[c] = __float2bfloat16(v - __bfloat162float(hi));
    }
    uint4* dh = reinterpret_cast<uint4*>(g_p6h + (size_t)g * 64);
    uint4* dl = reinterpret_cast<uint4*>(g_p6l + (size_t)g * 64);
    const uint4* sh = reinterpret_cast<const uint4*>(h);
    const uint4* sl = reinterpret_cast<const uint4*>(l);
#pragma unroll
    for (int i = 0; i < 8; i++) { dh[i] = sh[i]; dl[i] = sl[i]; }
}

// ============================================================
// wprep_all: all 8 layers' weights -> per-lane mma B-fragments
// (same fragment layout as validated in R10)
// ============================================================
__global__ void wprep_all_k(const float* w0, const float* w1, const float* w2,
                            const float* w3, const float* w4, const float* w5,
                            const float* w6, const float* w7)
{
    const int segoff[8] = {0, 9216, 46080, 82944, 119808, 156672, 193536, 230400};
    const int segsz[8]  = {9216, 36864, 36864, 36864, 36864, 36864, 36864, 147456};
    const int seg = blockIdx.x >> 4;
    const int KS = (seg == 0) ? 1 : 4;
    const int NT = (seg == 7) ? 32 : 8;
    const int OCs = (seg == 7) ? 225 : 64;
    const int ICs = (seg == 0) ? 6 : 64;
    const float* w;
    switch (seg) {
        case 0: w = w0; break; case 1: w = w1; break; case 2: w = w2; break;
        case 3: w = w3; break; case 4: w = w4; break; case 5: w = w5; break;
        case 6: w = w6; break; default: w = w7; break;
    }
    const int n = segsz[seg];
    const int dstoff = segoff[seg];
    for (int i = (blockIdx.x & 15) * 256 + threadIdx.x; i < n; i += 16 * 256) {
        int rem = i;
        int tap   = rem / (2 * KS * NT * 64); rem -= tap * (2 * KS * NT * 64);
        int plane = rem / (KS * NT * 64);     rem -= plane * (KS * NT * 64);
        int q     = rem / (NT * 64);          rem -= q * (NT * 64);
        int ntile = rem / 64;                 rem -= ntile * 64;
        int lane = rem >> 1, reg = rem & 1;
        int nn = ntile * 8 + (lane >> 2);
        int k0 = q * 16 + (lane & 3) * 2 + reg * 8;
        u32 outv = 0;
#pragma unroll
        for (int e = 0; e < 2; e++) {
            int k = k0 + e;
            float v = (nn < OCs && k < ICs) ? w[((size_t)nn * ICs + k) * 9 + tap] : 0.f;
            __nv_bfloat16 hb = __float2bfloat16(v);
            __nv_bfloat16 ob = (plane == 0) ? hb : __float2bfloat16(v - __bfloat162float(hb));
            unsigned short bits = *reinterpret_cast<unsigned short*>(&ob);
            outv |= ((u32)bits) << (16 * e);
        }
        g_wfrag[dstoff + i] = outv;
    }
}

// ============================================================
// convS: 3x3 conv as implicit GEMM, single-stage smem.
// Stage 3 y-planes of 130 rows once; dx shift = ldmatrix row offset.
// Block 256 thr (8 warps 4Mx2N), tile 128px x 64oc.
// 3-pass bf16 hi/lo -> fp32 acc.
// ============================================================
template<int KS, int NT, bool RELU, bool RESID, bool OUTM>
__global__ __launch_bounds__(256, 2)
void convS_k(const __nv_bfloat16* __restrict__ inh, const __nv_bfloat16* __restrict__ inl,
             const __nv_bfloat16* __restrict__ rh,  const __nv_bfloat16* __restrict__ rl,
             __nv_bfloat16* __restrict__ outh, __nv_bfloat16* __restrict__ outl,
             float* __restrict__ outf, const float* __restrict__ bias,
             const u32* __restrict__ bfrag)
{
    extern __shared__ char smem[];
    const u32 sbase = smem_u32(smem);
    const int tid   = threadIdx.x;
    const int lane  = tid & 31;
    const int warp  = tid >> 5;
    const int warpM = warp & 3, warpN = warp >> 2;

    const int x0 = blockIdx.x * 128;
    const int y  = blockIdx.y;
    int b = blockIdx.z, chunk = 0;
    if (OUTM) { chunk = b & 3; b >>= 2; }
    const size_t bbase = (size_t)b * HWP;

    // ---- stage 3 y-planes once ----
    for (int i = tid; i < 3 * 130 * 8; i += 256) {
        int pl  = i / 1040;
        int rem = i - pl * 1040;
        int row = rem >> 3, cc = rem & 7;
        int gy = y + pl - 1, gx = x0 + row - 1;
        bool ok = (unsigned)gy < HH && (unsigned)gx < WW;
        uint4 vh = make_uint4(0, 0, 0, 0), vl = vh;
        if (ok) {
            size_t gi = (bbase + (size_t)gy * WW + gx) * 64 + cc * 8;
            vh = *reinterpret_cast<const uint4*>(inh + gi);
            vl = *reinterpret_cast<const uint4*>(inl + gi);
        }
        u32 so = pl * PLANE_STRIDE + SWZ128((u32)(row * 128 + cc * 16));
        *reinterpret_cast<uint4*>(smem + so)          = vh;
        *reinterpret_cast<uint4*>(smem + so + LO_OFF) = vl;
    }
    __syncthreads();

    float acc[2][4][4];
#pragma unroll
    for (int mt = 0; mt < 2; mt++)
#pragma unroll
        for (int nt = 0; nt < 4; nt++)
#pragma unroll
            for (int e = 0; e < 4; e++) acc[mt][nt][e] = 0.f;

    const int r16 = lane & 15, tk = lane >> 4;

#pragma unroll
    for (int dy = 0; dy < 3; dy++) {
        const u32 aH = sbase + dy * PLANE_STRIDE;
#pragma unroll
        for (int dx = 0; dx < 3; dx++) {
            const int tap = dy * 3 + dx;
#pragma unroll
            for (int q = 0; q < KS; q++) {
                u32 ah[2][4], al[2][4];
#pragma unroll
                for (int mt = 0; mt < 2; mt++) {
                    int row = warpM * 32 + mt * 16 + r16 + dx;   // px + dx (halo -1 baked in)
                    u32 off = SWZ128((u32)(row * 128 + q * 32 + tk * 16));
                    LDSM4(ah[mt], aH + off);
                    LDSM4(al[mt], aH + LO_OFF + off);
                }
#pragma unroll
                for (int nt = 0; nt < 4; nt++) {
                    int ntg = chunk * 8 + warpN * 4 + nt;
                    const u32* bpH = bfrag + (((size_t)(tap * 2 + 0) * KS + q) * NT + ntg) * 64 + lane * 2;
                    const u32* bpL = bfrag + (((size_t)(tap * 2 + 1) * KS + q) * NT + ntg) * 64 + lane * 2;
                    u32 bh0 = bpH[0], bh1 = bpH[1];
                    u32 bl0 = bpL[0], bl1 = bpL[1];
#pragma unroll
                    for (int mt = 0; mt < 2; mt++) {
                        MMA16816(acc[mt][nt], ah[mt], bh0, bh1);
                        MMA16816(acc[mt][nt], ah[mt], bl0, bl1);
                        MMA16816(acc[mt][nt], al[mt], bh0, bh1);
                    }
                }
            }
        }
    }

    // ---- epilogue ----
#pragma unroll
    for (int nt = 0; nt < 4; nt++) {
        int oc = (OUTM ? chunk * 64 : 0) + warpN * 32 + nt * 8 + (lane & 3) * 2;
        float bz0, bz1;
        if (OUTM) {
            bz0 = (oc < 225) ? bias[oc] : 0.f;
            bz1 = (oc + 1 < 225) ? bias[oc + 1] : 0.f;
        } else {
            bz0 = bias[oc]; bz1 = bias[oc + 1];
        }
#pragma unroll
        for (int mt = 0; mt < 2; mt++) {
#pragma unroll
            for (int rr = 0; rr < 2; rr++) {
                int m = warpM * 32 + mt * 16 + (lane >> 2) + rr * 8;
                size_t pb = bbase + (size_t)y * WW + x0 + m;
                float v0 = acc[mt][nt][rr * 2 + 0] + bz0;
                float v1 = acc[mt][nt][rr * 2 + 1] + bz1;
                if (OUTM) {
                    if (oc < 228)
                        *reinterpret_cast<float2*>(outf + pb * CPAD + oc) = make_float2(v0, v1);
                } else {
                    size_t ei = pb * 64 + oc;
                    if (RESID) {
                        u32 hh = *reinterpret_cast<const u32*>(rh + ei);
                        u32 ll = *reinterpret_cast<const u32*>(rl + ei);
                        __nv_bfloat162 h2 = *reinterpret_cast<__nv_bfloat162*>(&hh);
                        __nv_bfloat162 l2 = *reinterpret_cast<__nv_bfloat162*>(&ll);
                        v0 += __bfloat162float(h2.x) + __bfloat162float(l2.x);
                        v1 += __bfloat162float(h2.y) + __bfloat162float(l2.y);
                    }
                    if (RELU) { v0 = fmaxf(v0, 0.f); v1 = fmaxf(v1, 0.f); }
                    __nv_bfloat16 h0 = __float2bfloat16(v0);
                    __nv_bfloat16 h1 = __float2bfloat16(v1);
                    __nv_bfloat16 l0 = __float2bfloat16(v0 - __bfloat162float(h0));
                    __nv_bfloat16 l1 = __float2bfloat16(v1 - __bfloat162float(h1));
                    __nv_bfloat162 hv; hv.x = h0; hv.y = h1;
                    __nv_bfloat162 lv; lv.x = l0; lv.y = l1;
                    *reinterpret_cast<__nv_bfloat162*>(outh + ei) = hv;
                    *reinterpret_cast<__nv_bfloat162*>(outl + ei) = lv;
                }
            }
        }
    }
}

// ============================================================
// kpn: per-pixel softmax(|core|) over 225 taps + 15x15 filter
// ============================================================
__global__ __launch_bounds__(128)
void kpn2_k(const float* __restrict__ data, float* __restrict__ pred)
{
    __shared__ float sd[3][15][144];
    const int tid = threadIdx.x;
    const int x0 = blockIdx.x * 128;
    const int y  = blockIdx.y;
    const int b  = blockIdx.z;

    for (int i = tid; i < 3 * 15 * 142; i += 128) {
        int c = i / (15 * 142);
        int r = (i - c * 15 * 142) / 142;
        int q = i - c * 15 * 142 - r * 142;
        int gy = y - 7 + r, gx = x0 - 7 + q;
        float v = 0.0f;
        if ((unsigned)gy < HH && (unsigned)gx < WW)
            v = data[((size_t)(b * 3 + c)) * HWP + gy * WW + gx];
        sd[c][r][q] = v;
    }
    __syncthreads();

    const int px = tid;
    const float4* cr = reinterpret_cast<const float4*>(
        g_core2 + ((size_t)b * HWP + (size_t)y * WW + x0 + px) * CPAD);

    float S = 0.f, P0 = 0.f, P1 = 0.f, P2 = 0.f;
    int ki = 0, kj = 0;
#pragma unroll 1
    for (int q = 0; q < 57; q++) {
        float4 f = cr[q];
        float fv[4] = {f.x, f.y, f.z, f.w};
#pragma unroll
        for (int s = 0; s < 4; s++) {
            int t = q * 4 + s;
            if (t < 225) {
                float w = __expf(fabsf(fv[s]));
                S  += w;
                P0 += w * sd[0][ki][px + kj];
                P1 += w * sd[1][ki][px + kj];
                P2 += w * sd[2][ki][px + kj];
                if (++kj == 15) { kj = 0; ki++; }
            }
        }
    }
    float inv = 1.0f / S;
    size_t o = (size_t)b * 3 * HWP + (size_t)y * WW + x0 + px;
    pred[o]           = P0 * inv;
    pred[o + HWP]     = P1 * inv;
    pred[o + 2 * HWP] = P2 * inv;
}

// ============================================================
// launch
// ============================================================
template<typename T>
static T* sym(const void* s) { void* p = nullptr; cudaGetSymbolAddress(&p, s); return (T*)p; }

extern "C" void kernel_launch(void* const* d_in, const int* in_sizes, int n_in,
                              void* d_out, int out_size)
{
    const float* dwe     = (const float*)d_in[0];
    const float* data    = (const float*)d_in[1];
    const float* w_first = (const float*)d_in[2];
    const float* b_first = (const float*)d_in[3];
    const float* w1a = (const float*)d_in[4];  const float* b1a = (const float*)d_in[5];
    const float* w1b = (const float*)d_in[6];  const float* b1b = (const float*)d_in[7];
    const float* w2a = (const float*)d_in[8];  const float* b2a = (const float*)d_in[9];
    const float* w2b = (const float*)d_in[10]; const float* b2b = (const float*)d_in[11];
    const float* w3a = (const float*)d_in[12]; const float* b3a = (const float*)d_in[13];
    const float* w3b = (const float*)d_in[14]; const float* b3b = (const float*)d_in[15];
    const float* w_out = (const float*)d_in[16]; const float* b_out = (const float*)d_in[17];

    __nv_bfloat16* p6h = sym<__nv_bfloat16>(g_p6h); __nv_bfloat16* p6l = sym<__nv_bfloat16>(g_p6l);
    __nv_bfloat16* pAh = sym<__nv_bfloat16>(g_pAh); __nv_bfloat16* pAl = sym<__nv_bfloat16>(g_pAl);
    __nv_bfloat16* pBh = sym<__nv_bfloat16>(g_pBh); __nv_bfloat16* pBl = sym<__nv_bfloat16>(g_pBl);
    __nv_bfloat16* pCh = sym<__nv_bfloat16>(g_pCh); __nv_bfloat16* pCl = sym<__nv_bfloat16>(g_pCl);
    float* core2 = sym<float>(g_core2);
    const u32* wf = sym<u32>(g_wfrag);

    static bool once = false;
    if (!once) {
        cudaFuncSetAttribute(convS_k<1, 8, false, false, false>, cudaFuncAttributeMaxDynamicSharedMemorySize, SMEM_BYTES);
        cudaFuncSetAttribute(convS_k<4, 8, true,  false, false>, cudaFuncAttributeMaxDynamicSharedMemorySize, SMEM_BYTES);
        cudaFuncSetAttribute(convS_k<4, 8, false, true,  false>, cudaFuncAttributeMaxDynamicSharedMemorySize, SMEM_BYTES);
        cudaFuncSetAttribute(convS_k<4, 32, false, false, true>, cudaFuncAttributeMaxDynamicSharedMemorySize, SMEM_BYTES);
        once = true;
    }

    pack6_k<<<NPIX / 256, 256>>>(dwe);
    wprep_all_k<<<128, 256>>>(w_first, w1a, w1b, w2a, w2b, w3a, w3b, w_out);

    // passthrough early (independent of compute chain)
    cudaMemcpyAsync(d_out, data, (size_t)BB * 3 * HWP * sizeof(float),
                    cudaMemcpyDeviceToDevice, 0);

    dim3 grid(2, 256, 4), blk(256);
    convS_k<1, 8, false, false, false><<<grid, blk, SMEM_BYTES>>>(p6h, p6l, nullptr, nullptr, pAh, pAl, nullptr, b_first, wf + 0);
    convS_k<4, 8, true,  false, false><<<grid, blk, SMEM_BYTES>>>(pAh, pAl, nullptr, nullptr, pBh, pBl, nullptr, b1a, wf + 9216);
    convS_k<4, 8, false, true,  false><<<grid, blk, SMEM_BYTES>>>(pBh, pBl, pAh, pAl, pCh, pCl, nullptr, b1b, wf + 46080);
    convS_k<4, 8, true,  false, false><<<grid, blk, SMEM_BYTES>>>(pCh, pCl, nullptr, nullptr, pBh, pBl, nullptr, b2a, wf + 82944);
    convS_k<4, 8, false, true,  false><<<grid, blk, SMEM_BYTES>>>(pBh, pBl, pCh, pCl, pAh, pAl, nullptr, b2b, wf + 119808);
    convS_k<4, 8, true,  false, false><<<grid, blk, SMEM_BYTES>>>(pAh, pAl, nullptr, nullptr, pBh, pBl, nullptr, b3a, wf + 156672);
    convS_k<4, 8, false, true,  false><<<grid, blk, SMEM_BYTES>>>(pBh, pBl, pAh, pAl, pCh, pCl, nullptr, b3b, wf + 193536);

    dim3 gridO(2, 256, 16);
    convS_k<4, 32, false, false, true><<<gridO, blk, SMEM_BYTES>>>(pCh, pCl, nullptr, nullptr, nullptr, nullptr, core2, b_out, wf + 230400);

    kpn2_k<<<dim3(2, 256, 4), 128>>>(data, (float*)d_out + (size_t)BB * 3 * HWP);
}

// round 12
// speedup vs baseline: 3.9924x; 1.2594x over previous
#include <cuda_runtime.h>
#include <cuda_fp16.h>
#include <cstdint>
#include <cstddef>

typedef unsigned int u32;
typedef unsigned long long u64;

#define BB 4
#define HH 256
#define WW 256
#define HWP (HH * WW)
#define NPIX (BB * HWP)
#define CPAD 228

// ---------------- device global scratch ----------------
__device__ __half g_p6h[(size_t)NPIX * 64], g_p6l[(size_t)NPIX * 64];
__device__ __half g_pAh[(size_t)NPIX * 64], g_pAl[(size_t)NPIX * 64];
__device__ __half g_pBh[(size_t)NPIX * 64], g_pBl[(size_t)NPIX * 64];
__device__ __half g_pCh[(size_t)NPIX * 64], g_pCl[(size_t)NPIX * 64];
__device__ float  g_core2[(size_t)NPIX * CPAD];
__device__ u32    g_wfrag[188928];

#define SWZ128(o) ((o) ^ (((o) >> 3) & 0x70))

__device__ __forceinline__ u32 smem_u32(const void* p) {
    u32 a;
    asm("{ .reg .u64 t; cvta.to.shared.u64 t, %1; cvt.u32.u64 %0, t; }" : "=r"(a) : "l"(p));
    return a;
}

#define LDSM4(r, a) asm volatile( \
    "ldmatrix.sync.aligned.m8n8.x4.shared.b16 {%0,%1,%2,%3}, [%4];" \
    : "=r"((r)[0]), "=r"((r)[1]), "=r"((r)[2]), "=r"((r)[3]) : "r"(a))

#define MMAF16(d, a, b0v, b1v) asm volatile( \
    "mma.sync.aligned.m16n8k16.row.col.f32.f16.f16.f32 " \
    "{%0,%1,%2,%3}, {%4,%5,%6,%7}, {%8,%9}, {%0,%1,%2,%3};" \
    : "+f"((d)[0]), "+f"((d)[1]), "+f"((d)[2]), "+f"((d)[3]) \
    : "r"((a)[0]), "r"((a)[1]), "r"((a)[2]), "r"((a)[3]), "r"(b0v), "r"(b1v))

// smem plane geometry: 3 planes (dy), each hi+lo; rows 0..129 <-> gx = x0-1..x0+128
#define PLANE_STRIDE 34816
#define LO_OFF       17408
#define SMEM_BYTES   (3 * PLANE_STRIDE)   // 104448

// fast exp(x), x >= 0, via 2^t polynomial (FMA pipe, no MUFU)
__device__ __forceinline__ float fexp_pos(float x)
{
    float t = fminf(x * 1.4426950408889634f, 126.0f);
    float n = rintf(t);
    float f = t - n;
    float p = 1.33336e-3f;
    p = fmaf(p, f, 9.61812e-3f);
    p = fmaf(p, f, 5.55041e-2f);
    p = fmaf(p, f, 2.40227e-1f);
    p = fmaf(p, f, 6.93147e-1f);
    p = fmaf(p, f, 1.0f);
    float sc = __int_as_float(((int)n + 127) << 23);
    return p * sc;
}

// ============================================================
// pack6: data_with_est [B,6,H,W] fp32 -> NHWC-64 fp16 hi/lo
// ============================================================
__global__ __launch_bounds__(256) void pack6_k(const float* __restrict__ in)
{
    int g = blockIdx.x * 256 + threadIdx.x;
    int b = g >> 16, p = g & 65535;
    alignas(16) __half h[64], l[64];
#pragma unroll
    for (int c = 0; c < 64; c++) { h[c] = __float2half(0.f); l[c] = __float2half(0.f); }
#pragma unroll
    for (int c = 0; c < 6; c++) {
        float v = in[((size_t)b * 6 + c) * HWP + p];
        __half hi = __float2half(v);
        h[c] = hi;
        l[c] = __float2half(v - __half2float(hi));
    }
    uint4* dh = reinterpret_cast<uint4*>(g_p6h + (size_t)g * 64);
    uint4* dl = reinterpret_cast<uint4*>(g_p6l + (size_t)g * 64);
    const uint4* sh = reinterpret_cast<const uint4*>(h);
    const uint4* sl = reinterpret_cast<const uint4*>(l);
#pragma unroll
    for (int i = 0; i < 8; i++) { dh[i] = sh[i]; dl[i] = sl[i]; }
}

// ============================================================
// wprep_all: all 8 layers' weights -> per-lane mma B-fragments
// single fp16 plane: idx = (((tap*KS + q)*NT + ntile)*64 + lane*2 + reg)
// value {B[k0][n], B[k0+1][n]}, k0 = q*16+(lane%4)*2+reg*8, n = ntile*8+lane/4
// ============================================================
__global__ void wprep_all_k(const float* w0, const float* w1, const float* w2,
                            const float* w3, const float* w4, const float* w5,
                            const float* w6, const float* w7)
{
    const int segoff[8] = {0, 4608, 23040, 41472, 59904, 78336, 96768, 115200};
    const int segsz[8]  = {4608, 18432, 18432, 18432, 18432, 18432, 18432, 73728};
    const int seg = blockIdx.x >> 4;
    const int KS = (seg == 0) ? 1 : 4;
    const int NT = (seg == 7) ? 32 : 8;
    const int OCs = (seg == 7) ? 225 : 64;
    const int ICs = (seg == 0) ? 6 : 64;
    const float* w;
    switch (seg) {
        case 0: w = w0; break; case 1: w = w1; break; case 2: w = w2; break;
        case 3: w = w3; break; case 4: w = w4; break; case 5: w = w5; break;
        case 6: w = w6; break; default: w = w7; break;
    }
    const int n = segsz[seg];
    const int dstoff = segoff[seg];
    for (int i = (blockIdx.x & 15) * 256 + threadIdx.x; i < n; i += 16 * 256) {
        int rem = i;
        int tap   = rem / (KS * NT * 64); rem -= tap * (KS * NT * 64);
        int q     = rem / (NT * 64);      rem -= q * (NT * 64);
        int ntile = rem / 64;             rem -= ntile * 64;
        int lane = rem >> 1, reg = rem & 1;
        int nn = ntile * 8 + (lane >> 2);
        int k0 = q * 16 + (lane & 3) * 2 + reg * 8;
        u32 outv = 0;
#pragma unroll
        for (int e = 0; e < 2; e++) {
            int k = k0 + e;
            float v = (nn < OCs && k < ICs) ? w[((size_t)nn * ICs + k) * 9 + tap] : 0.f;
            __half hb = __float2half(v);
            unsigned short bits = *reinterpret_cast<unsigned short*>(&hb);
            outv |= ((u32)bits) << (16 * e);
        }
        g_wfrag[dstoff + i] = outv;
    }
}

// ============================================================
// convS: 3x3 conv as implicit GEMM, single-stage smem, fp16.
// 2-pass hi/lo X (exact split), single-plane fp16 W.
// Block 256 thr (8 warps 4Mx2N), tile 128px x 64oc.
// ============================================================
template<int KS, int NT, bool RELU, bool RESID, bool OUTM>
__global__ __launch_bounds__(256, 2)
void convS_k(const __half* __restrict__ inh, const __half* __restrict__ inl,
             const __half* __restrict__ rh,  const __half* __restrict__ rl,
             __half* __restrict__ outh, __half* __restrict__ outl,
             float* __restrict__ outf, const float* __restrict__ bias,
             const u32* __restrict__ bfrag)
{
    extern __shared__ char smem[];
    const u32 sbase = smem_u32(smem);
    const int tid   = threadIdx.x;
    const int lane  = tid & 31;
    const int warp  = tid >> 5;
    const int warpM = warp & 3, warpN = warp >> 2;

    const int x0 = blockIdx.x * 128;
    const int y  = blockIdx.y;
    int b = blockIdx.z, chunk = 0;
    if (OUTM) { chunk = b & 3; b >>= 2; }
    const size_t bbase = (size_t)b * HWP;

    // ---- stage 3 y-planes once ----
    for (int i = tid; i < 3 * 130 * 8; i += 256) {
        int pl  = i / 1040;
        int rem = i - pl * 1040;
        int row = rem >> 3, cc = rem & 7;
        int gy = y + pl - 1, gx = x0 + row - 1;
        bool ok = (unsigned)gy < HH && (unsigned)gx < WW;
        uint4 vh = make_uint4(0, 0, 0, 0), vl = vh;
        if (ok) {
            size_t gi = (bbase + (size_t)gy * WW + gx) * 64 + cc * 8;
            vh = *reinterpret_cast<const uint4*>(inh + gi);
            vl = *reinterpret_cast<const uint4*>(inl + gi);
        }
        u32 so = pl * PLANE_STRIDE + SWZ128((u32)(row * 128 + cc * 16));
        *reinterpret_cast<uint4*>(smem + so)          = vh;
        *reinterpret_cast<uint4*>(smem + so + LO_OFF) = vl;
    }
    __syncthreads();

    float acc[2][4][4];
#pragma unroll
    for (int mt = 0; mt < 2; mt++)
#pragma unroll
        for (int nt = 0; nt < 4; nt++)
#pragma unroll
            for (int e = 0; e < 4; e++) acc[mt][nt][e] = 0.f;

    const int r16 = lane & 15, tk = lane >> 4;

#pragma unroll
    for (int dy = 0; dy < 3; dy++) {
        const u32 aH = sbase + dy * PLANE_STRIDE;
#pragma unroll
        for (int dx = 0; dx < 3; dx++) {
            const int tap = dy * 3 + dx;
#pragma unroll
            for (int q = 0; q < KS; q++) {
                u32 ah[2][4], al[2][4];
#pragma unroll
                for (int mt = 0; mt < 2; mt++) {
                    int row = warpM * 32 + mt * 16 + r16 + dx;
                    u32 off = SWZ128((u32)(row * 128 + q * 32 + tk * 16));
                    LDSM4(ah[mt], aH + off);
                    LDSM4(al[mt], aH + LO_OFF + off);
                }
#pragma unroll
                for (int nt = 0; nt < 4; nt++) {
                    int ntg = chunk * 8 + warpN * 4 + nt;
                    const u32* bp = bfrag + (((size_t)tap * KS + q) * NT + ntg) * 64 + lane * 2;
                    u32 b0 = bp[0], b1 = bp[1];
#pragma unroll
                    for (int mt = 0; mt < 2; mt++) {
                        MMAF16(acc[mt][nt], ah[mt], b0, b1);
                        MMAF16(acc[mt][nt], al[mt], b0, b1);
                    }
                }
            }
        }
    }

    // ---- epilogue ----
#pragma unroll
    for (int nt = 0; nt < 4; nt++) {
        int oc = (OUTM ? chunk * 64 : 0) + warpN * 32 + nt * 8 + (lane & 3) * 2;
        float bz0, bz1;
        if (OUTM) {
            bz0 = (oc < 225) ? bias[oc] : 0.f;
            bz1 = (oc + 1 < 225) ? bias[oc + 1] : 0.f;
        } else {
            bz0 = bias[oc]; bz1 = bias[oc + 1];
        }
#pragma unroll
        for (int mt = 0; mt < 2; mt++) {
#pragma unroll
            for (int rr = 0; rr < 2; rr++) {
                int m = warpM * 32 + mt * 16 + (lane >> 2) + rr * 8;
                size_t pb = bbase + (size_t)y * WW + x0 + m;
                float v0 = acc[mt][nt][rr * 2 + 0] + bz0;
                float v1 = acc[mt][nt][rr * 2 + 1] + bz1;
                if (OUTM) {
                    if (oc < 228)
                        *reinterpret_cast<float2*>(outf + pb * CPAD + oc) = make_float2(v0, v1);
                } else {
                    size_t ei = pb * 64 + oc;
                    if (RESID) {
                        u32 hh = *reinterpret_cast<const u32*>(rh + ei);
                        u32 ll = *reinterpret_cast<const u32*>(rl + ei);
                        __half2 h2 = *reinterpret_cast<__half2*>(&hh);
                        __half2 l2 = *reinterpret_cast<__half2*>(&ll);
                        v0 += __half2float(h2.x) + __half2float(l2.x);
                        v1 += __half2float(h2.y) + __half2float(l2.y);
                    }
                    if (RELU) { v0 = fmaxf(v0, 0.f); v1 = fmaxf(v1, 0.f); }
                    __half h0 = __float2half(v0);
                    __half h1 = __float2half(v1);
                    __half l0 = __float2half(v0 - __half2float(h0));
                    __half l1 = __float2half(v1 - __half2float(h1));
                    __half2 hv; hv.x = h0; hv.y = h1;
                    __half2 lv; lv.x = l0; lv.y = l1;
                    *reinterpret_cast<__half2*>(outh + ei) = hv;
                    *reinterpret_cast<__half2*>(outl + ei) = lv;
                }
            }
        }
    }
}

// ============================================================
// kpn: per-pixel softmax(|core|) over 225 taps + 15x15 filter
// exp via FMA-pipe polynomial (no MUFU bottleneck)
// ============================================================
__global__ __launch_bounds__(128)
void kpn2_k(const float* __restrict__ data, float* __restrict__ pred)
{
    __shared__ float sd[3][15][144];
    const int tid = threadIdx.x;
    const int x0 = blockIdx.x * 128;
    const int y  = blockIdx.y;
    const int b  = blockIdx.z;

    for (int i = tid; i < 3 * 15 * 142; i += 128) {
        int c = i / (15 * 142);
        int r = (i - c * 15 * 142) / 142;
        int q = i - c * 15 * 142 - r * 142;
        int gy = y - 7 + r, gx = x0 - 7 + q;
        float v = 0.0f;
        if ((unsigned)gy < HH && (unsigned)gx < WW)
            v = data[((size_t)(b * 3 + c)) * HWP + gy * WW + gx];
        sd[c][r][q] = v;
    }
    __syncthreads();

    const int px = tid;
    const float4* cr = reinterpret_cast<const float4*>(
        g_core2 + ((size_t)b * HWP + (size_t)y * WW + x0 + px) * CPAD);

    float S = 0.f, P0 = 0.f, P1 = 0.f, P2 = 0.f;
    int ki = 0, kj = 0;
#pragma unroll 1
    for (int q = 0; q < 57; q++) {
        float4 f = cr[q];
        float fv[4] = {f.x, f.y, f.z, f.w};
#pragma unroll
        for (int s = 0; s < 4; s++) {
            int t = q * 4 + s;
            if (t < 225) {
                float w = fexp_pos(fabsf(fv[s]));
                S  += w;
                P0 += w * sd[0][ki][px + kj];
                P1 += w * sd[1][ki][px + kj];
                P2 += w * sd[2][ki][px + kj];
                if (++kj == 15) { kj = 0; ki++; }
            }
        }
    }
    float inv = 1.0f / S;
    size_t o = (size_t)b * 3 * HWP + (size_t)y * WW + x0 + px;
    pred[o]           = P0 * inv;
    pred[o + HWP]     = P1 * inv;
    pred[o + 2 * HWP] = P2 * inv;
}

// ============================================================
// launch
// ============================================================
template<typename T>
static T* sym(const void* s) { void* p = nullptr; cudaGetSymbolAddress(&p, s); return (T*)p; }

extern "C" void kernel_launch(void* const* d_in, const int* in_sizes, int n_in,
                              void* d_out, int out_size)
{
    const float* dwe     = (const float*)d_in[0];
    const float* data    = (const float*)d_in[1];
    const float* w_first = (const float*)d_in[2];
    const float* b_first = (const float*)d_in[3];
    const float* w1a = (const float*)d_in[4];  const float* b1a = (const float*)d_in[5];
    const float* w1b = (const float*)d_in[6];  const float* b1b = (const float*)d_in[7];
    const float* w2a = (const float*)d_in[8];  const float* b2a = (const float*)d_in[9];
    const float* w2b = (const float*)d_in[10]; const float* b2b = (const float*)d_in[11];
    const float* w3a = (const float*)d_in[12]; const float* b3a = (const float*)d_in[13];
    const float* w3b = (const float*)d_in[14]; const float* b3b = (const float*)d_in[15];
    const float* w_out = (const float*)d_in[16]; const float* b_out = (const float*)d_in[17];

    __half* p6h = sym<__half>(g_p6h); __half* p6l = sym<__half>(g_p6l);
    __half* pAh = sym<__half>(g_pAh); __half* pAl = sym<__half>(g_pAl);
    __half* pBh = sym<__half>(g_pBh); __half* pBl = sym<__half>(g_pBl);
    __half* pCh = sym<__half>(g_pCh); __half* pCl = sym<__half>(g_pCl);
    float* core2 = sym<float>(g_core2);
    const u32* wf = sym<u32>(g_wfrag);

    static bool once = false;
    if (!once) {
        cudaFuncSetAttribute(convS_k<1, 8, false, false, false>, cudaFuncAttributeMaxDynamicSharedMemorySize, SMEM_BYTES);
        cudaFuncSetAttribute(convS_k<4, 8, true,  false, false>, cudaFuncAttributeMaxDynamicSharedMemorySize, SMEM_BYTES);
        cudaFuncSetAttribute(convS_k<4, 8, false, true,  false>, cudaFuncAttributeMaxDynamicSharedMemorySize, SMEM_BYTES);
        cudaFuncSetAttribute(convS_k<4, 32, false, false, true>, cudaFuncAttributeMaxDynamicSharedMemorySize, SMEM_BYTES);
        once = true;
    }

    pack6_k<<<NPIX / 256, 256>>>(dwe);
    wprep_all_k<<<128, 256>>>(w_first, w1a, w1b, w2a, w2b, w3a, w3b, w_out);

    cudaMemcpyAsync(d_out, data, (size_t)BB * 3 * HWP * sizeof(float),
                    cudaMemcpyDeviceToDevice, 0);

    dim3 grid(2, 256, 4), blk(256);
    convS_k<1, 8, false, false, false><<<grid, blk, SMEM_BYTES>>>(p6h, p6l, nullptr, nullptr, pAh, pAl, nullptr, b_first, wf + 0);
    convS_k<4, 8, true,  false, false><<<grid, blk, SMEM_BYTES>>>(pAh, pAl, nullptr, nullptr, pBh, pBl, nullptr, b1a, wf + 4608);
    convS_k<4, 8, false, true,  false><<<grid, blk, SMEM_BYTES>>>(pBh, pBl, pAh, pAl, pCh, pCl, nullptr, b1b, wf + 23040);
    convS_k<4, 8, true,  false, false><<<grid, blk, SMEM_BYTES>>>(pCh, pCl, nullptr, nullptr, pBh, pBl, nullptr, b2a, wf + 41472);
    convS_k<4, 8, false, true,  false><<<grid, blk, SMEM_BYTES>>>(pBh, pBl, pCh, pCl, pAh, pAl, nullptr, b2b, wf + 59904);
    convS_k<4, 8, true,  false, false><<<grid, blk, SMEM_BYTES>>>(pAh, pAl, nullptr, nullptr, pBh, pBl, nullptr, b3a, wf + 78336);
    convS_k<4, 8, false, true,  false><<<grid, blk, SMEM_BYTES>>>(pBh, pBl, pAh, pAl, pCh, pCl, nullptr, b3b, wf + 96768);

    dim3 gridO(2, 256, 16);
    convS_k<4, 32, false, false, true><<<gridO, blk, SMEM_BYTES>>>(pCh, pCl, nullptr, nullptr, nullptr, nullptr, core2, b_out, wf + 115200);

    kpn2_k<<<dim3(2, 256, 4), 128>>>(data, (float*)d_out + (size_t)BB * 3 * HWP);
}